// round 11
// baseline (speedup 1.0000x reference)
#include <cuda_runtime.h>
#include <cuda_fp16.h>
#include <cstdint>

// P=8, B=4, C=32, H=256, W=256, M1=M2=32
// rows R = P*B*C*H = 262144 ; pbc = P*B*C = 1024 ; cols (pbc,y) = 32768

typedef unsigned short ushort_t;

// ================= helpers =================
__device__ __forceinline__ uint32_t smem_u32(const void* p) {
    uint32_t a;
    asm("{ .reg .u64 t; cvta.to.shared.u64 t, %1; cvt.u32.u64 %0, t; }" : "=r"(a) : "l"(p));
    return a;
}
__device__ __forceinline__ void ldm4(uint32_t* r, uint32_t a) {
    asm volatile("ldmatrix.sync.aligned.m8n8.x4.shared.b16 {%0,%1,%2,%3}, [%4];"
                 : "=r"(r[0]), "=r"(r[1]), "=r"(r[2]), "=r"(r[3]) : "r"(a));
}
__device__ __forceinline__ void ldm4t(uint32_t* r, uint32_t a) {
    asm volatile("ldmatrix.sync.aligned.m8n8.x4.trans.shared.b16 {%0,%1,%2,%3}, [%4];"
                 : "=r"(r[0]), "=r"(r[1]), "=r"(r[2]), "=r"(r[3]) : "r"(a));
}
__device__ __forceinline__ void mma16816(float* c, const uint32_t* a, const uint32_t* b) {
    asm volatile("mma.sync.aligned.m16n8k16.row.col.f32.f16.f16.f32 "
                 "{%0,%1,%2,%3}, {%4,%5,%6,%7}, {%8,%9}, {%0,%1,%2,%3};"
                 : "+f"(c[0]), "+f"(c[1]), "+f"(c[2]), "+f"(c[3])
                 : "r"(a[0]), "r"(a[1]), "r"(a[2]), "r"(a[3]), "r"(b[0]), "r"(b[1]));
}
__device__ __forceinline__ void hsplit(float v, ushort_t& h, ushort_t& l) {
    __half hh = __float2half_rn(v);
    __half hl = __float2half_rn(v - __half2float(hh));
    h = __half_as_ushort(hh);
    l = __half_as_ushort(hl);
}
__device__ __forceinline__ ushort_t h1(float v) {
    return __half_as_ushort(__float2half_rn(v));
}
__device__ __forceinline__ void cpa16(uint32_t saddr, const void* g) {
    asm volatile("cp.async.cg.shared.global [%0], [%1], 16;" :: "r"(saddr), "l"(g));
}
#define CPA_COMMIT() asm volatile("cp.async.commit_group;" ::: "memory")
#define CPA_WAIT0()  asm volatile("cp.async.wait_group 0;" ::: "memory")

// ================= scratch =================
__device__ __align__(16) ushort_t g_Y [512u * 32768];       // fp16 [plane*256+h][pbc*32+y]
__device__ __align__(16) float    g_Z [128u * 32768];       // fp32 [plane*64+j][col]
__device__ __align__(16) ushort_t g_Z3[128u * 32768];       // fp16
__device__ __align__(16) ushort_t g_V [262144u * 64];       // fp16 [row][plane*32+y]
__device__ __align__(16) ushort_t g_B1h[128 * 64], g_B1l[128 * 64];    // [w][n]: n<32 cos(wn'), else -sin
__device__ __align__(16) ushort_t g_A2h[128 * 512], g_A2l[128 * 512];  // [row][k]
__device__ __align__(16) ushort_t g_A4h[512 * 128], g_A4l[512 * 128];  // [row][k]
__device__ __align__(16) ushort_t g_B5h[64 * 128], g_B5l[64 * 128];    // [k][w]: k<32 c_k cos, else -c_k sin

// ================= table init =================
__global__ void init_tables() {
    int t = blockIdx.x * 256 + threadIdx.x;   // 0..65535
    ushort_t h, l;
    if (t < 128 * 64) {     // B1 [w][n], w=0..127
        int w = t >> 6, n = t & 63, y = n & 31;
        int m = (w * y) & 255;
        double s, ct; sincospi(2.0 * m / 256.0, &s, &ct);
        hsplit((n < 32) ? (float)ct : (float)(-s), h, l);
        g_B1h[t] = h; g_B1l[t] = l;
    }
    {                       // A2 128x512
        int r = t >> 9, k = t & 511;
        int pk = k >> 8, hh = k & 255;
        int j = r & 63;
        int xr = (j < 32) ? j : (192 + j);
        int m = (xr * hh) & 255;
        double s, ct; sincospi(2.0 * m / 256.0, &s, &ct);
        float v;
        if (r < 64) v = (pk == 0) ? (float)ct : (float)s;
        else        v = (pk == 0) ? (float)(-s) : (float)ct;
        hsplit(v, h, l);
        g_A2h[t] = h; g_A2l[t] = l;
    }
    {                       // A4 512x128
        int r = t >> 7, c = t & 127;
        int pr = r >> 8, hh = r & 255;
        int pc = c >> 6, j = c & 63;
        int xr = (j < 32) ? j : (192 + j);
        int m = (xr * hh) & 255;
        double s, ct; sincospi(2.0 * m / 256.0, &s, &ct);
        float v;
        if (pr == 0) v = (pc == 0) ? (float)ct : (float)(-s);
        else         v = (pc == 0) ? (float)s  : (float)ct;
        hsplit(v, h, l);
        g_A4h[t] = h; g_A4l[t] = l;
    }
    if (t < 64 * 128) {     // B5 [k][w], w=0..127, UNSCALED (c_k); 1/65536 in epilogue
        int k = t >> 7, w = t & 127, kk = k & 31;
        int m = (kk * w) & 255;
        double s, ct; sincospi(2.0 * m / 256.0, &s, &ct);
        double coef = (kk == 0) ? 1.0 : 2.0;
        hsplit((k < 32) ? (float)(coef * ct) : (float)(-coef * s), h, l);
        g_B5h[t] = h; g_B5l[t] = l;
    }
}

// ================= S1: folded fwd-W DFT (K=128, even/odd split) =================
// Y_c[k] = u . cos + x[128]*(-1)^k ; Y_s[k] = v . (-sin) ; u/v = x[w] +/- x[256-w]
#define S1_PA 18432              // 128*72*2 per A plane (U, V)
#define S1_PB 9216               // 64*72*2 per B plane (hi, lo)
#define S1_SBUF 55296            // 2*PA + 2*PB
#define S1_CORR 110592           // after 2 buffers
#define S1_SMEM (S1_CORR + 512)

__global__ void __launch_bounds__(256, 2) s1fold(const float* __restrict__ X,
                                                 const ushort_t* __restrict__ Bh,
                                                 const ushort_t* __restrict__ Bl) {
    extern __shared__ char smem[];
    const uint32_t sb = smem_u32(smem);
    const int t = threadIdx.x, wid = t >> 5, lane = t & 31;
    const int wm = wid >> 1, wn = wid & 1;
    const long rowBase = (long)blockIdx.x * 128;
    float* corrS = reinterpret_cast<float*>(smem + S1_CORR);

    if (t < 128) corrS[t] = X[(rowBase + t) * 256 + 128];

    float acc[2][4][4];
#pragma unroll
    for (int i = 0; i < 2; ++i)
#pragma unroll
        for (int j = 0; j < 4; ++j)
#pragma unroll
            for (int q = 0; q < 4; ++q) acc[i][j][q] = 0.f;

    float fwd[32], mir[32];
    auto fetchB = [&](int kt, int buf) {
        const uint32_t bb = sb + buf * S1_SBUF + 2 * S1_PA;
#pragma unroll
        for (int f8 = 0; f8 < 2; ++f8) {
            int f = t + f8 * 256;
            int br = f >> 3, bc8 = f & 7;
            uint32_t off = (uint32_t)(br * 72 + bc8 * 8) * 2;
            cpa16(bb + off,          &Bh[(kt * 64 + br) * 64 + bc8 * 8]);
            cpa16(bb + S1_PB + off,  &Bl[(kt * 64 + br) * 64 + bc8 * 8]);
        }
    };
    auto loadA = [&](int kt) {
#pragma unroll
        for (int f4 = 0; f4 < 8; ++f4) {
            int f = t + f4 * 256;
            int ar = f >> 4, ac = f & 15;
            int w = kt * 64 + ac * 4;
            const float* rp = &X[(rowBase + ar) * 256];
            float4 v = *reinterpret_cast<const float4*>(&rp[w]);
            fwd[f4 * 4 + 0] = v.x; fwd[f4 * 4 + 1] = v.y;
            fwd[f4 * 4 + 2] = v.z; fwd[f4 * 4 + 3] = v.w;
#pragma unroll
            for (int q = 0; q < 4; ++q)
                mir[f4 * 4 + q] = (w + q == 0) ? 0.f : __ldg(&rp[256 - (w + q)]);
        }
    };
    auto storeA = [&](int kt, int buf) {
#pragma unroll
        for (int f4 = 0; f4 < 8; ++f4) {
            int f = t + f4 * 256;
            int ar = f >> 4, ac = f & 15;
            ushort_t uq[4], vq[4];
#pragma unroll
            for (int q = 0; q < 4; ++q) {
                float fw = fwd[f4 * 4 + q], mi = mir[f4 * 4 + q];
                uq[q] = h1(fw + mi);
                vq[q] = (kt == 0 && ac == 0 && q == 0) ? (ushort_t)0 : h1(fw - mi);
            }
            uint32_t off = buf * S1_SBUF + (uint32_t)(ar * 72 + ac * 4) * 2;
            *reinterpret_cast<uint2*>(smem + off) =
                make_uint2(uq[0] | ((uint32_t)uq[1] << 16), uq[2] | ((uint32_t)uq[3] << 16));
            *reinterpret_cast<uint2*>(smem + S1_PA + off) =
                make_uint2(vq[0] | ((uint32_t)vq[1] << 16), vq[2] | ((uint32_t)vq[3] << 16));
        }
    };
    auto compute = [&](int buf) {
        const uint32_t bb = sb + buf * S1_SBUF;
        const uint32_t ap = bb + (wn ? S1_PA : 0);
#pragma unroll
        for (int ks = 0; ks < 4; ++ks) {
            const int k0 = ks * 16;
            uint32_t a[2][4];
#pragma unroll
            for (int i = 0; i < 2; ++i) {
                int row = wm * 32 + i * 16 + (lane & 15);
                int col = k0 + ((lane >> 4) << 3);
                ldm4(a[i], ap + (uint32_t)(row * 72 + col) * 2);
            }
#pragma unroll
            for (int pr = 0; pr < 2; ++pr) {
                uint32_t b0[4], b1[4];
                int krow = k0 + ((lane >> 3) & 1) * 8 + (lane & 7);
                int coln = wn * 32 + (pr * 2 + (lane >> 4)) * 8;
                uint32_t boff = bb + 2 * S1_PA + (uint32_t)(krow * 72 + coln) * 2;
                ldm4t(b0, boff);
                ldm4t(b1, boff + S1_PB);
#pragma unroll
                for (int i = 0; i < 2; ++i)
#pragma unroll
                    for (int nn = 0; nn < 2; ++nn) {
                        float* c = acc[i][pr * 2 + nn];
                        mma16816(c, a[i], b0 + nn * 2);
                        mma16816(c, a[i], b1 + nn * 2);
                    }
            }
        }
    };

    // KT = 2, manual schedule
    fetchB(0, 0);
    CPA_COMMIT();
    loadA(0);
    CPA_WAIT0();
    storeA(0, 0);
    __syncthreads();
    fetchB(1, 1);
    CPA_COMMIT();
    loadA(1);
    compute(0);
    storeA(1, 1);
    CPA_WAIT0();
    __syncthreads();
    compute(1);

    // epilogue: stage, add x[128]*(-1)^k to cos cols, fp16 plane scatter
    __syncthreads();
    float* stage = reinterpret_cast<float*>(smem);
    const int g = lane >> 2, tq = lane & 3;
#pragma unroll
    for (int i = 0; i < 2; ++i)
#pragma unroll
        for (int j = 0; j < 4; ++j) {
            const float* c = acc[i][j];
            int row = wm * 32 + i * 16 + g;
            int col = wn * 32 + j * 8 + tq * 2;
            *reinterpret_cast<float2*>(&stage[row * 68 + col])       = make_float2(c[0], c[1]);
            *reinterpret_cast<float2*>(&stage[(row + 8) * 68 + col]) = make_float2(c[2], c[3]);
        }
    __syncthreads();
    const long pbc = rowBase >> 8;
    const int hb = (int)(rowBase & 255);
#pragma unroll
    for (int it = 0; it < 8; ++it) {
        int idx = t + it * 256;
        int r = idx >> 4, c4 = idx & 15;
        float4 v = *reinterpret_cast<float4*>(&stage[r * 68 + c4 * 4]);
        if (c4 < 8) {   // cos cols 0..31: k = c4*4+q, (-1)^k = +,-,+,-
            float cr = corrS[r];
            v.x += cr; v.y -= cr; v.z += cr; v.w -= cr;
        }
        int plane = c4 >> 3, y = (c4 & 7) * 4;
        ushort_t q0 = h1(v.x), q1 = h1(v.y), q2 = h1(v.z), q3 = h1(v.w);
        long addr = (long)(plane * 256 + hb + r) * 32768L + pbc * 32 + y;
        *reinterpret_cast<uint2*>(&g_Y[addr]) =
            make_uint2(q0 | ((uint32_t)q1 << 16), q2 | ((uint32_t)q3 << 16));
    }
}

// ================= S2/S4: presplit-A x single-fp16-B GEMM (BM=128,BN=64,BK=64) =================
// CMODE 0: row-major f32.  CMODE 2: -> g_V fp16 emit [(pbc*256+h)][plane*32+y].
template<long KDIM, long NTOT, int CMODE>
__global__ void __launch_bounds__(256, 2) mgemmH(
    const ushort_t* __restrict__ Ahg, const ushort_t* __restrict__ Alg,
    const ushort_t* __restrict__ Bg, float* __restrict__ Cf)
{
    constexpr int PA = 128 * 72 * 2, PB = 64 * 72 * 2;
    constexpr int SBUF = 2 * PA + PB;   // 46080
    constexpr long KT = KDIM / 64;
    extern __shared__ char smem[];
    const uint32_t sb = smem_u32(smem);
    const int t = threadIdx.x, wid = t >> 5, lane = t & 31;
    const int wm = wid >> 1, wn = wid & 1;
    const long rowBase = (long)blockIdx.x * 128;
    const long colBase = (long)blockIdx.y * 64;

    float acc[2][4][4];
#pragma unroll
    for (int i = 0; i < 2; ++i)
#pragma unroll
        for (int j = 0; j < 4; ++j)
#pragma unroll
            for (int q = 0; q < 4; ++q) acc[i][j][q] = 0.f;

    auto fetchAsync = [&](long k0, int buf) {
        const uint32_t bb = sb + buf * SBUF;
#pragma unroll
        for (int f8 = 0; f8 < 4; ++f8) {
            int f = t + f8 * 256;
            int ar = f >> 3, ac8 = f & 7;
            uint32_t off = (uint32_t)(ar * 72 + ac8 * 8) * 2;
            cpa16(bb + off,      &Ahg[(rowBase + ar) * KDIM + k0 + ac8 * 8]);
            cpa16(bb + PA + off, &Alg[(rowBase + ar) * KDIM + k0 + ac8 * 8]);
        }
#pragma unroll
        for (int f8 = 0; f8 < 2; ++f8) {
            int f = t + f8 * 256;
            int br = f >> 3, bc8 = f & 7;
            uint32_t off = (uint32_t)(br * 72 + bc8 * 8) * 2;
            cpa16(bb + 2 * PA + off, &Bg[(k0 + br) * NTOT + colBase + bc8 * 8]);
        }
    };
    auto compute = [&](int buf) {
        const uint32_t bb = sb + buf * SBUF;
#pragma unroll
        for (int ks = 0; ks < 4; ++ks) {
            const int k0 = ks * 16;
            uint32_t a0[2][4], a1[2][4];
#pragma unroll
            for (int i = 0; i < 2; ++i) {
                int row = wm * 32 + i * 16 + (lane & 15);
                int col = k0 + ((lane >> 4) << 3);
                uint32_t off = (uint32_t)(row * 72 + col) * 2;
                ldm4(a0[i], bb + off);
                ldm4(a1[i], bb + PA + off);
            }
#pragma unroll
            for (int pr = 0; pr < 2; ++pr) {
                uint32_t b0[4];
                int krow = k0 + ((lane >> 3) & 1) * 8 + (lane & 7);
                int coln = wn * 32 + (pr * 2 + (lane >> 4)) * 8;
                ldm4t(b0, bb + 2 * PA + (uint32_t)(krow * 72 + coln) * 2);
#pragma unroll
                for (int i = 0; i < 2; ++i)
#pragma unroll
                    for (int nn = 0; nn < 2; ++nn) {
                        float* c = acc[i][pr * 2 + nn];
                        mma16816(c, a0[i], b0 + nn * 2);
                        mma16816(c, a1[i], b0 + nn * 2);
                    }
            }
        }
    };

    fetchAsync(0, 0);
    CPA_COMMIT();
    CPA_WAIT0();
    __syncthreads();
#pragma unroll 1
    for (long kt = 0; kt < KT; ++kt) {
        const int cur = (int)(kt & 1);
        const bool more = (kt + 1 < KT);
        if (more) {
            fetchAsync((kt + 1) * 64, cur ^ 1);
            CPA_COMMIT();
        }
        compute(cur);
        if (more) {
            CPA_WAIT0();
            __syncthreads();
        }
    }

    const int g = lane >> 2, tq = lane & 3;
    if constexpr (CMODE == 0) {
#pragma unroll
        for (int i = 0; i < 2; ++i)
#pragma unroll
            for (int j = 0; j < 4; ++j) {
                const float* c = acc[i][j];
                long r0 = rowBase + wm * 32 + i * 16 + g;
                long c0 = colBase + wn * 32 + j * 8 + tq * 2;
                *reinterpret_cast<float2*>(&Cf[r0 * NTOT + c0])       = make_float2(c[0], c[1]);
                *reinterpret_cast<float2*>(&Cf[(r0 + 8) * NTOT + c0]) = make_float2(c[2], c[3]);
            }
    } else {
#pragma unroll
        for (int i = 0; i < 2; ++i)
#pragma unroll
            for (int j = 0; j < 4; ++j) {
                const float* c = acc[i][j];
                long r0 = rowBase + wm * 32 + i * 16 + g;
                long c0 = colBase + wn * 32 + j * 8 + tq * 2;
                long pbc = c0 >> 5, y = c0 & 31;
#pragma unroll
                for (int rr = 0; rr < 2; ++rr) {
                    long r = r0 + rr * 8;
                    long plane = r >> 8, h = r & 255;
                    long addr = (pbc * 256 + h) * 64 + plane * 32 + y;
                    ushort_t q0 = h1(c[rr * 2]), q1 = h1(c[rr * 2 + 1]);
                    *reinterpret_cast<uint32_t*>(&g_V[addr]) = q0 | ((uint32_t)q1 << 16);
                }
            }
    }
}

// ================= S5: folded inv-W DFT (N=128 + butterfly) =================
#define S5_PA 9216               // 64*72*2
#define S5_PB 17408              // 64*136*2 per plane
#define S5_SMEM (S5_PA + 2 * S5_PB)   // 44032

__global__ void __launch_bounds__(256, 2) s5fold(const ushort_t* __restrict__ V,
                                                 const ushort_t* __restrict__ Bh,
                                                 const ushort_t* __restrict__ Bl,
                                                 float* __restrict__ out) {
    extern __shared__ char smem[];
    const uint32_t sb = smem_u32(smem);
    const int t = threadIdx.x, wid = t >> 5, lane = t & 31;
    const int wm = wid >> 2, wn = wid & 3;
    const long rowBase = (long)blockIdx.x * 64;

    // fetch A (V tile 64x64 fp16) and B (64x128 hi/lo)
#pragma unroll
    for (int f8 = 0; f8 < 2; ++f8) {
        int f = t + f8 * 256;
        int ar = f >> 3, ac8 = f & 7;
        cpa16(sb + (uint32_t)(ar * 72 + ac8 * 8) * 2, &V[(rowBase + ar) * 64 + ac8 * 8]);
    }
#pragma unroll
    for (int f8 = 0; f8 < 4; ++f8) {
        int f = t + f8 * 256;
        int br = f >> 4, bc8 = f & 15;
        uint32_t off = (uint32_t)(br * 136 + bc8 * 8) * 2;
        cpa16(sb + S5_PA + off,         &Bh[br * 128 + bc8 * 8]);
        cpa16(sb + S5_PA + S5_PB + off, &Bl[br * 128 + bc8 * 8]);
    }
    CPA_COMMIT();
    CPA_WAIT0();
    __syncthreads();

    float accE[2][4][4], accO[2][4][4];
#pragma unroll
    for (int i = 0; i < 2; ++i)
#pragma unroll
        for (int j = 0; j < 4; ++j)
#pragma unroll
            for (int q = 0; q < 4; ++q) { accE[i][j][q] = 0.f; accO[i][j][q] = 0.f; }

#pragma unroll
    for (int ks = 0; ks < 4; ++ks) {
        const int k0 = ks * 16;
        float (*acc)[4][4] = (ks < 2) ? accE : accO;
        uint32_t a[2][4];
#pragma unroll
        for (int i = 0; i < 2; ++i) {
            int row = wm * 32 + i * 16 + (lane & 15);
            int col = k0 + ((lane >> 4) << 3);
            ldm4(a[i], sb + (uint32_t)(row * 72 + col) * 2);
        }
#pragma unroll
        for (int pr = 0; pr < 2; ++pr) {
            uint32_t b0[4], b1[4];
            int krow = k0 + ((lane >> 3) & 1) * 8 + (lane & 7);
            int coln = wn * 32 + (pr * 2 + (lane >> 4)) * 8;
            uint32_t boff = sb + S5_PA + (uint32_t)(krow * 136 + coln) * 2;
            ldm4t(b0, boff);
            ldm4t(b1, boff + S5_PB);
#pragma unroll
            for (int i = 0; i < 2; ++i)
#pragma unroll
                for (int nn = 0; nn < 2; ++nn) {
                    float* c = acc[i][pr * 2 + nn];
                    mma16816(c, a[i], b0 + nn * 2);
                    mma16816(c, a[i], b1 + nn * 2);
                }
        }
    }

    // butterfly epilogue: out[w] = (E+O)*SC  (w 0..127); out[256-w] = (E-O)*SC (w 1..127)
    constexpr float SC = 1.0f / 65536.0f;
    float* stage = reinterpret_cast<float*>(smem);
    const int g = lane >> 2, tq = lane & 3;
    __syncthreads();
    // pass 1: E+O
#pragma unroll
    for (int i = 0; i < 2; ++i)
#pragma unroll
        for (int j = 0; j < 4; ++j) {
            const float* e = accE[i][j];
            const float* o = accO[i][j];
            int row = wm * 32 + i * 16 + g;
            int col = wn * 32 + j * 8 + tq * 2;
            *reinterpret_cast<float2*>(&stage[row * 132 + col]) =
                make_float2(e[0] + o[0], e[1] + o[1]);
            *reinterpret_cast<float2*>(&stage[(row + 8) * 132 + col]) =
                make_float2(e[2] + o[2], e[3] + o[3]);
        }
    __syncthreads();
#pragma unroll
    for (int it = 0; it < 8; ++it) {
        int idx = t + it * 256;
        int r = idx >> 5, c4 = idx & 31;
        float4 v = *reinterpret_cast<float4*>(&stage[r * 132 + c4 * 4]);
        v.x *= SC; v.y *= SC; v.z *= SC; v.w *= SC;
        *reinterpret_cast<float4*>(&out[(rowBase + r) * 256 + c4 * 4]) = v;
    }
    __syncthreads();
    // pass 2: E-O reversed -> cols 128..255 (col 128 garbage; fixed by fixup128)
#pragma unroll
    for (int i = 0; i < 2; ++i)
#pragma unroll
        for (int j = 0; j < 4; ++j) {
            const float* e = accE[i][j];
            const float* o = accO[i][j];
            int row = wm * 32 + i * 16 + g;
            int col = wn * 32 + j * 8 + tq * 2;     // w = col, col+1
            int m0 = 128 - col;                     // stage index for w
            stage[row * 132 + m0]           = e[0] - o[0];
            stage[row * 132 + m0 - 1]       = e[1] - o[1];
            stage[(row + 8) * 132 + m0]     = e[2] - o[2];
            stage[(row + 8) * 132 + m0 - 1] = e[3] - o[3];
        }
    __syncthreads();
#pragma unroll
    for (int it = 0; it < 8; ++it) {
        int idx = t + it * 256;
        int r = idx >> 5, c4 = idx & 31;
        float4 v = *reinterpret_cast<float4*>(&stage[r * 132 + c4 * 4]);
        v.x *= SC; v.y *= SC; v.z *= SC; v.w *= SC;
        *reinterpret_cast<float4*>(&out[(rowBase + r) * 256 + 128 + c4 * 4]) = v;
    }
}

// ================= fixup: out[:,128] = sum_k c_k (-1)^k Vre[k] / 65536 =================
__global__ void fixup128(const ushort_t* __restrict__ V, float* __restrict__ out) {
    long row = (long)blockIdx.x * 256 + threadIdx.x;
    float acc = 0.f;
#pragma unroll
    for (int k = 0; k < 32; ++k) {
        float v = __half2float(__ushort_as_half(V[row * 64 + k]));
        float ck = (k == 0) ? 1.f : ((k & 1) ? -2.f : 2.f);
        acc += ck * v;
    }
    out[row * 256 + 128] = acc * (1.0f / 65536.0f);
}

// ================= channel mix (round-9 version; reads g_Z, emits g_Z3 fp16) =================
__global__ void __launch_bounds__(256, 2) chanmix(const float* __restrict__ Z,
                                                  const float* __restrict__ w1re,
                                                  const float* __restrict__ w1im,
                                                  const float* __restrict__ w4re,
                                                  const float* __restrict__ w4im) {
    __shared__ float Zs[2][4][32][32];
    __shared__ float Ws[2][2][2][32][32];
    const int t = threadIdx.x;
    const int p = blockIdx.x >> 6;
    const int j = blockIdx.x & 63;
    const int x = j & 31;
    const float* wre = (j < 32) ? w1re : w4re;
    const float* wim = (j < 32) ? w1im : w4im;

#pragma unroll
    for (int pass = 0; pass < 8; ++pass) {
        int f = t + pass * 256;
        int plane = f >> 10;
        int rem = f & 1023;
        int bi = rem >> 3;
        int y4 = rem & 7;
        float4 v = *reinterpret_cast<const float4*>(
            &Z[(size_t)(plane * 64 + j) * 32768 + (size_t)(p * 128 + bi) * 32 + y4 * 4]);
        *reinterpret_cast<float4*>(&Zs[plane][bi >> 5][bi & 31][y4 * 4]) = v;
    }
    __syncthreads();

    const int og = t >> 7;
    const int t2 = t & 127;
    const int bb = (t2 >> 5) & 3;
    const int y  = t & 31;

    float zre[32], zim[32];
#pragma unroll
    for (int i = 0; i < 32; ++i) {
        zre[i] = Zs[0][bb][i][y];
        zim[i] = Zs[1][bb][i][y];
    }

    auto fetchW = [&](int o, int buf) {
#pragma unroll
        for (int pass = 0; pass < 4; ++pass) {
            int f = t2 + pass * 128;
            int plane = f >> 8;
            int i = (f >> 3) & 31;
            int seg = f & 7;
            const float* wp = plane ? wim : wre;
            const float* gp = &wp[((((size_t)(i * 32 + o)) * 8 + p) * 32 + x) * 32 + seg * 4];
            cpa16(smem_u32(&Ws[og][buf][plane][i][seg * 4]), gp);
        }
    };

    fetchW(og * 16, 0);
    CPA_COMMIT();
    CPA_WAIT0();
    __syncthreads();

#pragma unroll 1
    for (int ol = 0; ol < 16; ++ol) {
        const int o = og * 16 + ol;
        const bool more = (ol + 1 < 16);
        if (more) {
            fetchW(o + 1, (ol + 1) & 1);
            CPA_COMMIT();
        }
        const int buf = ol & 1;
        float accre = 0.f, accim = 0.f;
#pragma unroll
        for (int i = 0; i < 32; ++i) {
            float wr = Ws[og][buf][0][i][y];
            float wi = Ws[og][buf][1][i][y];
            accre += zre[i] * wr - zim[i] * wi;
            accim += zre[i] * wi + zim[i] * wr;
        }
        size_t col = (size_t)(p * 128 + bb * 32 + o) * 32 + y;
        g_Z3[(size_t)j * 32768 + col]        = h1(accre);
        g_Z3[(size_t)(64 + j) * 32768 + col] = h1(accim);
        if (more) {
            CPA_WAIT0();
            __syncthreads();
        }
    }
}

// ================= launch =================
extern "C" void kernel_launch(void* const* d_in, const int* in_sizes, int n_in,
                              void* d_out, int out_size) {
    const float* x    = (const float*)d_in[0];
    const float* w1re = (const float*)d_in[1];
    const float* w1im = (const float*)d_in[2];
    const float* w4re = (const float*)d_in[3];
    const float* w4im = (const float*)d_in[4];
    float* out = (float*)d_out;

    void *pY, *pZ, *pZ3, *pV;
    void *pB1h, *pB1l, *pA2h, *pA2l, *pA4h, *pA4l, *pB5h, *pB5l;
    cudaGetSymbolAddress(&pY,   g_Y);
    cudaGetSymbolAddress(&pZ,   g_Z);
    cudaGetSymbolAddress(&pZ3,  g_Z3);
    cudaGetSymbolAddress(&pV,   g_V);
    cudaGetSymbolAddress(&pB1h, g_B1h);
    cudaGetSymbolAddress(&pB1l, g_B1l);
    cudaGetSymbolAddress(&pA2h, g_A2h);
    cudaGetSymbolAddress(&pA2l, g_A2l);
    cudaGetSymbolAddress(&pA4h, g_A4h);
    cudaGetSymbolAddress(&pA4l, g_A4l);
    cudaGetSymbolAddress(&pB5h, g_B5h);
    cudaGetSymbolAddress(&pB5l, g_B5l);

    auto s2k = mgemmH<512L, 32768L, 0>;
    auto s4k = mgemmH<128L, 32768L, 2>;
    cudaFuncSetAttribute(s1fold, cudaFuncAttributeMaxDynamicSharedMemorySize, S1_SMEM);
    cudaFuncSetAttribute(s2k, cudaFuncAttributeMaxDynamicSharedMemorySize, 92160);
    cudaFuncSetAttribute(s4k, cudaFuncAttributeMaxDynamicSharedMemorySize, 92160);
    cudaFuncSetAttribute(s5fold, cudaFuncAttributeMaxDynamicSharedMemorySize, S5_SMEM);

    init_tables<<<256, 256>>>();

    // S1 folded: Y = fwd-W DFT of x (K=128 even/odd)
    s1fold<<<2048, 256, S1_SMEM>>>(x, (const ushort_t*)pB1h, (const ushort_t*)pB1l);

    // S2: Z(128x32768) = A2(128x512) * Y(512x32768)
    s2k<<<dim3(1, 512), 256, 92160>>>((const ushort_t*)pA2h, (const ushort_t*)pA2l,
                                      (const ushort_t*)pY, (float*)pZ);

    // S3: channel mixing
    chanmix<<<512, 256>>>((const float*)pZ, w1re, w1im, w4re, w4im);

    // S4: V(512x32768) = A4(512x128) * Z3(128x32768) -> g_V fp16
    s4k<<<dim3(4, 512), 256, 92160>>>((const ushort_t*)pA4h, (const ushort_t*)pA4l,
                                      (const ushort_t*)pZ3, nullptr);

    // S5 folded: out = inv-W DFT with butterfly (cols 0..255, col 128 garbage)
    s5fold<<<4096, 256, S5_SMEM>>>((const ushort_t*)pV, (const ushort_t*)pB5h,
                                   (const ushort_t*)pB5l, out);

    // fixup col 128
    fixup128<<<1024, 256>>>((const ushort_t*)pV, out);
}

// round 12
// speedup vs baseline: 1.0447x; 1.0447x over previous
#include <cuda_runtime.h>
#include <cuda_fp16.h>
#include <cstdint>

// P=8, B=4, C=32, H=256, W=256, M1=M2=32
// rows R = P*B*C*H = 262144 ; pbc = P*B*C = 1024 ; cols (pbc,y) = 32768

typedef unsigned short ushort_t;

// ================= helpers =================
__device__ __forceinline__ uint32_t smem_u32(const void* p) {
    uint32_t a;
    asm("{ .reg .u64 t; cvta.to.shared.u64 t, %1; cvt.u32.u64 %0, t; }" : "=r"(a) : "l"(p));
    return a;
}
__device__ __forceinline__ void ldm4(uint32_t* r, uint32_t a) {
    asm volatile("ldmatrix.sync.aligned.m8n8.x4.shared.b16 {%0,%1,%2,%3}, [%4];"
                 : "=r"(r[0]), "=r"(r[1]), "=r"(r[2]), "=r"(r[3]) : "r"(a));
}
__device__ __forceinline__ void ldm4t(uint32_t* r, uint32_t a) {
    asm volatile("ldmatrix.sync.aligned.m8n8.x4.trans.shared.b16 {%0,%1,%2,%3}, [%4];"
                 : "=r"(r[0]), "=r"(r[1]), "=r"(r[2]), "=r"(r[3]) : "r"(a));
}
__device__ __forceinline__ void mma16816(float* c, const uint32_t* a, const uint32_t* b) {
    asm volatile("mma.sync.aligned.m16n8k16.row.col.f32.f16.f16.f32 "
                 "{%0,%1,%2,%3}, {%4,%5,%6,%7}, {%8,%9}, {%0,%1,%2,%3};"
                 : "+f"(c[0]), "+f"(c[1]), "+f"(c[2]), "+f"(c[3])
                 : "r"(a[0]), "r"(a[1]), "r"(a[2]), "r"(a[3]), "r"(b[0]), "r"(b[1]));
}
__device__ __forceinline__ void hsplit(float v, ushort_t& h, ushort_t& l) {
    __half hh = __float2half_rn(v);
    __half hl = __float2half_rn(v - __half2float(hh));
    h = __half_as_ushort(hh);
    l = __half_as_ushort(hl);
}
__device__ __forceinline__ ushort_t h1(float v) {
    return __half_as_ushort(__float2half_rn(v));
}
__device__ __forceinline__ void cpa16(uint32_t saddr, const void* g) {
    asm volatile("cp.async.cg.shared.global [%0], [%1], 16;" :: "r"(saddr), "l"(g));
}
#define CPA_COMMIT() asm volatile("cp.async.commit_group;" ::: "memory")
#define CPA_WAIT0()  asm volatile("cp.async.wait_group 0;" ::: "memory")

// ================= scratch =================
__device__ __align__(16) ushort_t g_Y [512u * 32768];       // fp16 [plane*256+h][pbc*32+y]
__device__ __align__(16) float    g_Z [128u * 32768];       // fp32 [plane*64+j][col]
__device__ __align__(16) ushort_t g_Z3[128u * 32768];       // fp16
__device__ __align__(16) ushort_t g_V [262144u * 64];       // fp16 [row][plane*32+y]
__device__ __align__(16) ushort_t g_B1h[128 * 64], g_B1l[128 * 64];    // [w][n]: n<32 cos, else -sin
__device__ __align__(16) ushort_t g_A2h[128 * 512], g_A2l[128 * 512];  // [row][k]
__device__ __align__(16) ushort_t g_A4h[512 * 128], g_A4l[512 * 128];  // [row][k]
__device__ __align__(16) ushort_t g_T5h[64 * 256], g_T5l[64 * 256];    // [k|32+k][w] UNSCALED (c_k)

// ================= table init =================
__global__ void init_tables() {
    int t = blockIdx.x * 256 + threadIdx.x;   // 0..65535
    ushort_t h, l;
    if (t < 128 * 64) {     // B1 [w][n], w=0..127
        int w = t >> 6, n = t & 63, y = n & 31;
        int m = (w * y) & 255;
        double s, ct; sincospi(2.0 * m / 256.0, &s, &ct);
        hsplit((n < 32) ? (float)ct : (float)(-s), h, l);
        g_B1h[t] = h; g_B1l[t] = l;
    }
    {                       // A2 128x512
        int r = t >> 9, k = t & 511;
        int pk = k >> 8, hh = k & 255;
        int j = r & 63;
        int xr = (j < 32) ? j : (192 + j);
        int m = (xr * hh) & 255;
        double s, ct; sincospi(2.0 * m / 256.0, &s, &ct);
        float v;
        if (r < 64) v = (pk == 0) ? (float)ct : (float)s;
        else        v = (pk == 0) ? (float)(-s) : (float)ct;
        hsplit(v, h, l);
        g_A2h[t] = h; g_A2l[t] = l;
    }
    {                       // A4 512x128
        int r = t >> 7, c = t & 127;
        int pr = r >> 8, hh = r & 255;
        int pc = c >> 6, j = c & 63;
        int xr = (j < 32) ? j : (192 + j);
        int m = (xr * hh) & 255;
        double s, ct; sincospi(2.0 * m / 256.0, &s, &ct);
        float v;
        if (pr == 0) v = (pc == 0) ? (float)ct : (float)(-s);
        else         v = (pc == 0) ? (float)s  : (float)ct;
        hsplit(v, h, l);
        g_A4h[t] = h; g_A4l[t] = l;
    }
    if (t < 64 * 256) {     // T5 [k|32+k][w], w=0..255, UNSCALED (c_k); 1/65536 in S5 epilogue
        int r = t >> 8, w = t & 255, k = r & 31;
        int m = (k * w) & 255;
        double s, ct; sincospi(2.0 * m / 256.0, &s, &ct);
        double coef = (k == 0) ? 1.0 : 2.0;
        hsplit((r < 32) ? (float)(coef * ct) : (float)(-coef * s), h, l);
        g_T5h[t] = h; g_T5l[t] = l;
    }
}

// ================= S1: folded fwd-W DFT (K=128, even/odd split, float4 mirror loads) =================
// Y_c[k] = u . cos + x[128]*(-1)^k ; Y_s[k] = v . (-sin) ; u/v = x[w] +/- x[256-w]
#define S1_PA 18432              // 128*72*2 per A plane (U, V)
#define S1_PB 9216               // 64*72*2 per B plane (hi, lo)
#define S1_SBUF 55296            // 2*PA + 2*PB
#define S1_CORR 110592
#define S1_SMEM (S1_CORR + 512)

__global__ void __launch_bounds__(256, 2) s1fold(const float* __restrict__ X,
                                                 const ushort_t* __restrict__ Bh,
                                                 const ushort_t* __restrict__ Bl) {
    extern __shared__ char smem[];
    const uint32_t sb = smem_u32(smem);
    const int t = threadIdx.x, wid = t >> 5, lane = t & 31;
    const int wm = wid >> 1, wn = wid & 1;
    const long rowBase = (long)blockIdx.x * 128;
    float* corrS = reinterpret_cast<float*>(smem + S1_CORR);

    if (t < 128) corrS[t] = X[(rowBase + t) * 256 + 128];

    float acc[2][4][4];
#pragma unroll
    for (int i = 0; i < 2; ++i)
#pragma unroll
        for (int j = 0; j < 4; ++j)
#pragma unroll
            for (int q = 0; q < 4; ++q) acc[i][j][q] = 0.f;

    float fwd[32], mir[32];
    auto fetchB = [&](int kt, int buf) {
        const uint32_t bb = sb + buf * S1_SBUF + 2 * S1_PA;
#pragma unroll
        for (int f8 = 0; f8 < 2; ++f8) {
            int f = t + f8 * 256;
            int br = f >> 3, bc8 = f & 7;
            uint32_t off = (uint32_t)(br * 72 + bc8 * 8) * 2;
            cpa16(bb + off,         &Bh[(kt * 64 + br) * 64 + bc8 * 8]);
            cpa16(bb + S1_PB + off, &Bl[(kt * 64 + br) * 64 + bc8 * 8]);
        }
    };
    // fwd: float4 at w. mirror: float4 at 252-w gives (252-w,253-w,254-w,255-w);
    // mir[0]=rp[256-w] comes from lane-1's m4.x via shfl (same row for ac>=1).
    auto loadA = [&](int kt) {
#pragma unroll
        for (int f4 = 0; f4 < 8; ++f4) {
            int f = t + f4 * 256;
            int ar = f >> 4, ac = f & 15;
            int w = kt * 64 + ac * 4;
            const float* rp = &X[(rowBase + ar) * 256];
            float4 v = *reinterpret_cast<const float4*>(&rp[w]);
            fwd[f4 * 4 + 0] = v.x; fwd[f4 * 4 + 1] = v.y;
            fwd[f4 * 4 + 2] = v.z; fwd[f4 * 4 + 3] = v.w;
            float4 m4 = *reinterpret_cast<const float4*>(&rp[252 - w]);
            float m0 = __shfl_up_sync(0xffffffffu, m4.x, 1);
            if (ac == 0) m0 = (kt == 0) ? 0.f : __ldg(&rp[192]);
            mir[f4 * 4 + 0] = m0;
            mir[f4 * 4 + 1] = m4.w;
            mir[f4 * 4 + 2] = m4.z;
            mir[f4 * 4 + 3] = m4.y;
        }
    };
    auto storeA = [&](int kt, int buf) {
#pragma unroll
        for (int f4 = 0; f4 < 8; ++f4) {
            int f = t + f4 * 256;
            int ar = f >> 4, ac = f & 15;
            ushort_t uq[4], vq[4];
#pragma unroll
            for (int q = 0; q < 4; ++q) {
                float fw = fwd[f4 * 4 + q], mi = mir[f4 * 4 + q];
                uq[q] = h1(fw + mi);
                vq[q] = h1(fw - mi);
            }
            uint32_t off = buf * S1_SBUF + (uint32_t)(ar * 72 + ac * 4) * 2;
            *reinterpret_cast<uint2*>(smem + off) =
                make_uint2(uq[0] | ((uint32_t)uq[1] << 16), uq[2] | ((uint32_t)uq[3] << 16));
            *reinterpret_cast<uint2*>(smem + S1_PA + off) =
                make_uint2(vq[0] | ((uint32_t)vq[1] << 16), vq[2] | ((uint32_t)vq[3] << 16));
        }
    };
    auto compute = [&](int buf) {
        const uint32_t bb = sb + buf * S1_SBUF;
        const uint32_t ap = bb + (wn ? S1_PA : 0);
#pragma unroll
        for (int ks = 0; ks < 4; ++ks) {
            const int k0 = ks * 16;
            uint32_t a[2][4];
#pragma unroll
            for (int i = 0; i < 2; ++i) {
                int row = wm * 32 + i * 16 + (lane & 15);
                int col = k0 + ((lane >> 4) << 3);
                ldm4(a[i], ap + (uint32_t)(row * 72 + col) * 2);
            }
#pragma unroll
            for (int pr = 0; pr < 2; ++pr) {
                uint32_t b0[4], b1[4];
                int krow = k0 + ((lane >> 3) & 1) * 8 + (lane & 7);
                int coln = wn * 32 + (pr * 2 + (lane >> 4)) * 8;
                uint32_t boff = bb + 2 * S1_PA + (uint32_t)(krow * 72 + coln) * 2;
                ldm4t(b0, boff);
                ldm4t(b1, boff + S1_PB);
#pragma unroll
                for (int i = 0; i < 2; ++i)
#pragma unroll
                    for (int nn = 0; nn < 2; ++nn) {
                        float* c = acc[i][pr * 2 + nn];
                        mma16816(c, a[i], b0 + nn * 2);
                        mma16816(c, a[i], b1 + nn * 2);
                    }
            }
        }
    };

    // KT = 2, manual schedule
    fetchB(0, 0);
    CPA_COMMIT();
    loadA(0);
    CPA_WAIT0();
    storeA(0, 0);
    __syncthreads();
    fetchB(1, 1);
    CPA_COMMIT();
    loadA(1);
    compute(0);
    storeA(1, 1);
    CPA_WAIT0();
    __syncthreads();
    compute(1);

    // epilogue: stage, add x[128]*(-1)^k to cos cols, fp16 plane scatter
    __syncthreads();
    float* stage = reinterpret_cast<float*>(smem);
    const int g = lane >> 2, tq = lane & 3;
#pragma unroll
    for (int i = 0; i < 2; ++i)
#pragma unroll
        for (int j = 0; j < 4; ++j) {
            const float* c = acc[i][j];
            int row = wm * 32 + i * 16 + g;
            int col = wn * 32 + j * 8 + tq * 2;
            *reinterpret_cast<float2*>(&stage[row * 68 + col])       = make_float2(c[0], c[1]);
            *reinterpret_cast<float2*>(&stage[(row + 8) * 68 + col]) = make_float2(c[2], c[3]);
        }
    __syncthreads();
    const long pbc = rowBase >> 8;
    const int hb = (int)(rowBase & 255);
#pragma unroll
    for (int it = 0; it < 8; ++it) {
        int idx = t + it * 256;
        int r = idx >> 4, c4 = idx & 15;
        float4 v = *reinterpret_cast<float4*>(&stage[r * 68 + c4 * 4]);
        if (c4 < 8) {   // cos cols: k = c4*4+q, (-1)^k = +,-,+,-
            float cr = corrS[r];
            v.x += cr; v.y -= cr; v.z += cr; v.w -= cr;
        }
        int plane = c4 >> 3, y = (c4 & 7) * 4;
        ushort_t q0 = h1(v.x), q1 = h1(v.y), q2 = h1(v.z), q3 = h1(v.w);
        long addr = (long)(plane * 256 + hb + r) * 32768L + pbc * 32 + y;
        *reinterpret_cast<uint2*>(&g_Y[addr]) =
            make_uint2(q0 | ((uint32_t)q1 << 16), q2 | ((uint32_t)q3 << 16));
    }
}

// ================= S2/S4: presplit-A x single-fp16-B GEMM (BM=128,BN=64,BK=64) =================
// CMODE 0: row-major f32.  CMODE 2: -> g_V fp16 emit [(pbc*256+h)][plane*32+y].
template<long KDIM, long NTOT, int CMODE>
__global__ void __launch_bounds__(256, 2) mgemmH(
    const ushort_t* __restrict__ Ahg, const ushort_t* __restrict__ Alg,
    const ushort_t* __restrict__ Bg, float* __restrict__ Cf)
{
    constexpr int PA = 128 * 72 * 2, PB = 64 * 72 * 2;
    constexpr int SBUF = 2 * PA + PB;   // 46080
    constexpr long KT = KDIM / 64;
    extern __shared__ char smem[];
    const uint32_t sb = smem_u32(smem);
    const int t = threadIdx.x, wid = t >> 5, lane = t & 31;
    const int wm = wid >> 1, wn = wid & 1;
    const long rowBase = (long)blockIdx.x * 128;
    const long colBase = (long)blockIdx.y * 64;

    float acc[2][4][4];
#pragma unroll
    for (int i = 0; i < 2; ++i)
#pragma unroll
        for (int j = 0; j < 4; ++j)
#pragma unroll
            for (int q = 0; q < 4; ++q) acc[i][j][q] = 0.f;

    auto fetchAsync = [&](long k0, int buf) {
        const uint32_t bb = sb + buf * SBUF;
#pragma unroll
        for (int f8 = 0; f8 < 4; ++f8) {
            int f = t + f8 * 256;
            int ar = f >> 3, ac8 = f & 7;
            uint32_t off = (uint32_t)(ar * 72 + ac8 * 8) * 2;
            cpa16(bb + off,      &Ahg[(rowBase + ar) * KDIM + k0 + ac8 * 8]);
            cpa16(bb + PA + off, &Alg[(rowBase + ar) * KDIM + k0 + ac8 * 8]);
        }
#pragma unroll
        for (int f8 = 0; f8 < 2; ++f8) {
            int f = t + f8 * 256;
            int br = f >> 3, bc8 = f & 7;
            uint32_t off = (uint32_t)(br * 72 + bc8 * 8) * 2;
            cpa16(bb + 2 * PA + off, &Bg[(k0 + br) * NTOT + colBase + bc8 * 8]);
        }
    };
    auto compute = [&](int buf) {
        const uint32_t bb = sb + buf * SBUF;
#pragma unroll
        for (int ks = 0; ks < 4; ++ks) {
            const int k0 = ks * 16;
            uint32_t a0[2][4], a1[2][4];
#pragma unroll
            for (int i = 0; i < 2; ++i) {
                int row = wm * 32 + i * 16 + (lane & 15);
                int col = k0 + ((lane >> 4) << 3);
                uint32_t off = (uint32_t)(row * 72 + col) * 2;
                ldm4(a0[i], bb + off);
                ldm4(a1[i], bb + PA + off);
            }
#pragma unroll
            for (int pr = 0; pr < 2; ++pr) {
                uint32_t b0[4];
                int krow = k0 + ((lane >> 3) & 1) * 8 + (lane & 7);
                int coln = wn * 32 + (pr * 2 + (lane >> 4)) * 8;
                ldm4t(b0, bb + 2 * PA + (uint32_t)(krow * 72 + coln) * 2);
#pragma unroll
                for (int i = 0; i < 2; ++i)
#pragma unroll
                    for (int nn = 0; nn < 2; ++nn) {
                        float* c = acc[i][pr * 2 + nn];
                        mma16816(c, a0[i], b0 + nn * 2);
                        mma16816(c, a1[i], b0 + nn * 2);
                    }
            }
        }
    };

    fetchAsync(0, 0);
    CPA_COMMIT();
    CPA_WAIT0();
    __syncthreads();
#pragma unroll 1
    for (long kt = 0; kt < KT; ++kt) {
        const int cur = (int)(kt & 1);
        const bool more = (kt + 1 < KT);
        if (more) {
            fetchAsync((kt + 1) * 64, cur ^ 1);
            CPA_COMMIT();
        }
        compute(cur);
        if (more) {
            CPA_WAIT0();
            __syncthreads();
        }
    }

    const int g = lane >> 2, tq = lane & 3;
    if constexpr (CMODE == 0) {
#pragma unroll
        for (int i = 0; i < 2; ++i)
#pragma unroll
            for (int j = 0; j < 4; ++j) {
                const float* c = acc[i][j];
                long r0 = rowBase + wm * 32 + i * 16 + g;
                long c0 = colBase + wn * 32 + j * 8 + tq * 2;
                *reinterpret_cast<float2*>(&Cf[r0 * NTOT + c0])       = make_float2(c[0], c[1]);
                *reinterpret_cast<float2*>(&Cf[(r0 + 8) * NTOT + c0]) = make_float2(c[2], c[3]);
            }
    } else {
#pragma unroll
        for (int i = 0; i < 2; ++i)
#pragma unroll
            for (int j = 0; j < 4; ++j) {
                const float* c = acc[i][j];
                long r0 = rowBase + wm * 32 + i * 16 + g;
                long c0 = colBase + wn * 32 + j * 8 + tq * 2;
                long pbc = c0 >> 5, y = c0 & 31;
#pragma unroll
                for (int rr = 0; rr < 2; ++rr) {
                    long r = r0 + rr * 8;
                    long plane = r >> 8, h = r & 255;
                    long addr = (pbc * 256 + h) * 64 + plane * 32 + y;
                    ushort_t q0 = h1(c[rr * 2]), q1 = h1(c[rr * 2 + 1]);
                    *reinterpret_cast<uint32_t*>(&g_V[addr]) = q0 | ((uint32_t)q1 << 16);
                }
            }
    }
}

// ================= S5 (round-10 proven): out = V(fp16) * T5(hi/lo), BM=64, BN=128, KT=1 =================
#define S5_PA 9216               // 64*72*2
#define S5_PB 17408              // 64*136*2 per plane
#define S5_SMEM (S5_PA + 2 * S5_PB)   // 44032

__global__ void __launch_bounds__(256, 2) s5gemm(const ushort_t* __restrict__ V,
                                                 const ushort_t* __restrict__ Bh,
                                                 const ushort_t* __restrict__ Bl,
                                                 float* __restrict__ out) {
    extern __shared__ char smem[];
    const uint32_t sb = smem_u32(smem);
    const int t = threadIdx.x, wid = t >> 5, lane = t & 31;
    const int wm = wid >> 2, wn = wid & 3;
    const long rowBase = (long)blockIdx.x * 64;
    const long colBase = (long)blockIdx.y * 128;

    // A: V tile 64x64 fp16 ; B: T5 64 x 128 (two planes)
#pragma unroll
    for (int f8 = 0; f8 < 2; ++f8) {
        int f = t + f8 * 256;
        int ar = f >> 3, ac8 = f & 7;
        cpa16(sb + (uint32_t)(ar * 72 + ac8 * 8) * 2, &V[(rowBase + ar) * 64 + ac8 * 8]);
    }
#pragma unroll
    for (int f8 = 0; f8 < 4; ++f8) {
        int f = t + f8 * 256;
        int br = f >> 4, bc8 = f & 15;
        uint32_t off = (uint32_t)(br * 136 + bc8 * 8) * 2;
        cpa16(sb + S5_PA + off,         &Bh[br * 256 + colBase + bc8 * 8]);
        cpa16(sb + S5_PA + S5_PB + off, &Bl[br * 256 + colBase + bc8 * 8]);
    }
    CPA_COMMIT();
    CPA_WAIT0();
    __syncthreads();

    float acc[2][4][4];
#pragma unroll
    for (int i = 0; i < 2; ++i)
#pragma unroll
        for (int j = 0; j < 4; ++j)
#pragma unroll
            for (int q = 0; q < 4; ++q) acc[i][j][q] = 0.f;

#pragma unroll
    for (int ks = 0; ks < 4; ++ks) {
        const int k0 = ks * 16;
        uint32_t a[2][4];
#pragma unroll
        for (int i = 0; i < 2; ++i) {
            int row = wm * 32 + i * 16 + (lane & 15);
            int col = k0 + ((lane >> 4) << 3);
            ldm4(a[i], sb + (uint32_t)(row * 72 + col) * 2);
        }
#pragma unroll
        for (int pr = 0; pr < 2; ++pr) {
            uint32_t b0[4], b1[4];
            int krow = k0 + ((lane >> 3) & 1) * 8 + (lane & 7);
            int coln = wn * 32 + (pr * 2 + (lane >> 4)) * 8;
            uint32_t boff = sb + S5_PA + (uint32_t)(krow * 136 + coln) * 2;
            ldm4t(b0, boff);
            ldm4t(b1, boff + S5_PB);
#pragma unroll
            for (int i = 0; i < 2; ++i)
#pragma unroll
                for (int nn = 0; nn < 2; ++nn) {
                    float* c = acc[i][pr * 2 + nn];
                    mma16816(c, a[i], b0 + nn * 2);
                    mma16816(c, a[i], b1 + nn * 2);
                }
        }
    }

    // staged epilogue, scaled by 1/65536
    constexpr float SC = 1.0f / 65536.0f;
    float* stage = reinterpret_cast<float*>(smem + S5_PA);
    const int g = lane >> 2, tq = lane & 3;
    __syncthreads();
#pragma unroll
    for (int i = 0; i < 2; ++i)
#pragma unroll
        for (int j = 0; j < 4; ++j) {
            const float* c = acc[i][j];
            int row = wm * 32 + i * 16 + g;
            int col = wn * 32 + j * 8 + tq * 2;
            *reinterpret_cast<float2*>(&stage[row * 132 + col])       = make_float2(c[0], c[1]);
            *reinterpret_cast<float2*>(&stage[(row + 8) * 132 + col]) = make_float2(c[2], c[3]);
        }
    __syncthreads();
#pragma unroll
    for (int it = 0; it < 8; ++it) {
        int idx = t + it * 256;
        int r = idx >> 5, c4 = idx & 31;
        float4 v = *reinterpret_cast<float4*>(&stage[r * 132 + c4 * 4]);
        v.x *= SC; v.y *= SC; v.z *= SC; v.w *= SC;
        *reinterpret_cast<float4*>(&out[(rowBase + r) * 256 + colBase + c4 * 4]) = v;
    }
}

// ================= channel mix (proven; reads g_Z, emits g_Z3 fp16) =================
__global__ void __launch_bounds__(256, 2) chanmix(const float* __restrict__ Z,
                                                  const float* __restrict__ w1re,
                                                  const float* __restrict__ w1im,
                                                  const float* __restrict__ w4re,
                                                  const float* __restrict__ w4im) {
    __shared__ float Zs[2][4][32][32];
    __shared__ float Ws[2][2][2][32][32];
    const int t = threadIdx.x;
    const int p = blockIdx.x >> 6;
    const int j = blockIdx.x & 63;
    const int x = j & 31;
    const float* wre = (j < 32) ? w1re : w4re;
    const float* wim = (j < 32) ? w1im : w4im;

#pragma unroll
    for (int pass = 0; pass < 8; ++pass) {
        int f = t + pass * 256;
        int plane = f >> 10;
        int rem = f & 1023;
        int bi = rem >> 3;
        int y4 = rem & 7;
        float4 v = *reinterpret_cast<const float4*>(
            &Z[(size_t)(plane * 64 + j) * 32768 + (size_t)(p * 128 + bi) * 32 + y4 * 4]);
        *reinterpret_cast<float4*>(&Zs[plane][bi >> 5][bi & 31][y4 * 4]) = v;
    }
    __syncthreads();

    const int og = t >> 7;
    const int t2 = t & 127;
    const int bb = (t2 >> 5) & 3;
    const int y  = t & 31;

    float zre[32], zim[32];
#pragma unroll
    for (int i = 0; i < 32; ++i) {
        zre[i] = Zs[0][bb][i][y];
        zim[i] = Zs[1][bb][i][y];
    }

    auto fetchW = [&](int o, int buf) {
#pragma unroll
        for (int pass = 0; pass < 4; ++pass) {
            int f = t2 + pass * 128;
            int plane = f >> 8;
            int i = (f >> 3) & 31;
            int seg = f & 7;
            const float* wp = plane ? wim : wre;
            const float* gp = &wp[((((size_t)(i * 32 + o)) * 8 + p) * 32 + x) * 32 + seg * 4];
            cpa16(smem_u32(&Ws[og][buf][plane][i][seg * 4]), gp);
        }
    };

    fetchW(og * 16, 0);
    CPA_COMMIT();
    CPA_WAIT0();
    __syncthreads();

#pragma unroll 1
    for (int ol = 0; ol < 16; ++ol) {
        const int o = og * 16 + ol;
        const bool more = (ol + 1 < 16);
        if (more) {
            fetchW(o + 1, (ol + 1) & 1);
            CPA_COMMIT();
        }
        const int buf = ol & 1;
        float accre = 0.f, accim = 0.f;
#pragma unroll
        for (int i = 0; i < 32; ++i) {
            float wr = Ws[og][buf][0][i][y];
            float wi = Ws[og][buf][1][i][y];
            accre += zre[i] * wr - zim[i] * wi;
            accim += zre[i] * wi + zim[i] * wr;
        }
        size_t col = (size_t)(p * 128 + bb * 32 + o) * 32 + y;
        g_Z3[(size_t)j * 32768 + col]        = h1(accre);
        g_Z3[(size_t)(64 + j) * 32768 + col] = h1(accim);
        if (more) {
            CPA_WAIT0();
            __syncthreads();
        }
    }
}

// ================= launch =================
extern "C" void kernel_launch(void* const* d_in, const int* in_sizes, int n_in,
                              void* d_out, int out_size) {
    const float* x    = (const float*)d_in[0];
    const float* w1re = (const float*)d_in[1];
    const float* w1im = (const float*)d_in[2];
    const float* w4re = (const float*)d_in[3];
    const float* w4im = (const float*)d_in[4];
    float* out = (float*)d_out;

    void *pY, *pZ, *pZ3, *pV;
    void *pB1h, *pB1l, *pA2h, *pA2l, *pA4h, *pA4l, *pT5h, *pT5l;
    cudaGetSymbolAddress(&pY,   g_Y);
    cudaGetSymbolAddress(&pZ,   g_Z);
    cudaGetSymbolAddress(&pZ3,  g_Z3);
    cudaGetSymbolAddress(&pV,   g_V);
    cudaGetSymbolAddress(&pB1h, g_B1h);
    cudaGetSymbolAddress(&pB1l, g_B1l);
    cudaGetSymbolAddress(&pA2h, g_A2h);
    cudaGetSymbolAddress(&pA2l, g_A2l);
    cudaGetSymbolAddress(&pA4h, g_A4h);
    cudaGetSymbolAddress(&pA4l, g_A4l);
    cudaGetSymbolAddress(&pT5h, g_T5h);
    cudaGetSymbolAddress(&pT5l, g_T5l);

    auto s2k = mgemmH<512L, 32768L, 0>;
    auto s4k = mgemmH<128L, 32768L, 2>;
    cudaFuncSetAttribute(s1fold, cudaFuncAttributeMaxDynamicSharedMemorySize, S1_SMEM);
    cudaFuncSetAttribute(s2k, cudaFuncAttributeMaxDynamicSharedMemorySize, 92160);
    cudaFuncSetAttribute(s4k, cudaFuncAttributeMaxDynamicSharedMemorySize, 92160);
    cudaFuncSetAttribute(s5gemm, cudaFuncAttributeMaxDynamicSharedMemorySize, S5_SMEM);

    init_tables<<<256, 256>>>();

    // S1 folded: Y = fwd-W DFT of x (K=128 even/odd, float4 mirror loads)
    s1fold<<<2048, 256, S1_SMEM>>>(x, (const ushort_t*)pB1h, (const ushort_t*)pB1l);

    // S2: Z(128x32768) = A2(128x512) * Y(512x32768)
    s2k<<<dim3(1, 512), 256, 92160>>>((const ushort_t*)pA2h, (const ushort_t*)pA2l,
                                      (const ushort_t*)pY, (float*)pZ);

    // S3: channel mixing
    chanmix<<<512, 256>>>((const float*)pZ, w1re, w1im, w4re, w4im);

    // S4: V(512x32768) = A4(512x128) * Z3(128x32768) -> g_V fp16
    s4k<<<dim3(4, 512), 256, 92160>>>((const ushort_t*)pA4h, (const ushort_t*)pA4l,
                                      (const ushort_t*)pZ3, nullptr);

    // S5: out(262144x256) = V(262144x64) * T5(64x256), scaled in epilogue
    s5gemm<<<dim3(4096, 2), 256, S5_SMEM>>>((const ushort_t*)pV, (const ushort_t*)pT5h,
                                            (const ushort_t*)pT5l, out);
}

// round 13
// speedup vs baseline: 1.1970x; 1.1458x over previous
#include <cuda_runtime.h>
#include <cuda_fp16.h>
#include <cstdint>

// P=8, B=4, C=32, H=256, W=256, M1=M2=32
// rows R = P*B*C*H = 262144 ; pbc = P*B*C = 1024 ; cols (pbc,y) = 32768

typedef unsigned short ushort_t;

// ================= helpers =================
__device__ __forceinline__ uint32_t smem_u32(const void* p) {
    uint32_t a;
    asm("{ .reg .u64 t; cvta.to.shared.u64 t, %1; cvt.u32.u64 %0, t; }" : "=r"(a) : "l"(p));
    return a;
}
__device__ __forceinline__ void ldm4(uint32_t* r, uint32_t a) {
    asm volatile("ldmatrix.sync.aligned.m8n8.x4.shared.b16 {%0,%1,%2,%3}, [%4];"
                 : "=r"(r[0]), "=r"(r[1]), "=r"(r[2]), "=r"(r[3]) : "r"(a));
}
__device__ __forceinline__ void ldm4t(uint32_t* r, uint32_t a) {
    asm volatile("ldmatrix.sync.aligned.m8n8.x4.trans.shared.b16 {%0,%1,%2,%3}, [%4];"
                 : "=r"(r[0]), "=r"(r[1]), "=r"(r[2]), "=r"(r[3]) : "r"(a));
}
__device__ __forceinline__ void mma16816(float* c, const uint32_t* a, const uint32_t* b) {
    asm volatile("mma.sync.aligned.m16n8k16.row.col.f32.f16.f16.f32 "
                 "{%0,%1,%2,%3}, {%4,%5,%6,%7}, {%8,%9}, {%0,%1,%2,%3};"
                 : "+f"(c[0]), "+f"(c[1]), "+f"(c[2]), "+f"(c[3])
                 : "r"(a[0]), "r"(a[1]), "r"(a[2]), "r"(a[3]), "r"(b[0]), "r"(b[1]));
}
__device__ __forceinline__ void hsplit(float v, ushort_t& h, ushort_t& l) {
    __half hh = __float2half_rn(v);
    __half hl = __float2half_rn(v - __half2float(hh));
    h = __half_as_ushort(hh);
    l = __half_as_ushort(hl);
}
__device__ __forceinline__ ushort_t h1(float v) {
    return __half_as_ushort(__float2half_rn(v));
}
__device__ __forceinline__ void cpa16(uint32_t saddr, const void* g) {
    asm volatile("cp.async.cg.shared.global [%0], [%1], 16;" :: "r"(saddr), "l"(g));
}
#define CPA_COMMIT() asm volatile("cp.async.commit_group;" ::: "memory")
#define CPA_WAIT0()  asm volatile("cp.async.wait_group 0;" ::: "memory")

// ================= scratch =================
__device__ __align__(16) ushort_t g_Y [512u * 32768];       // fp16 [plane*256+h][pbc*32+y]
__device__ __align__(16) float    g_Z [128u * 32768];       // fp32 [plane*64+j][col]
__device__ __align__(16) ushort_t g_Z3[128u * 32768];       // fp16
__device__ __align__(16) ushort_t g_V [262144u * 64];       // fp16 [row][plane*32+y]
__device__ __align__(16) ushort_t g_T1[256 * 64];           // single fp16 [k=w][n]
__device__ __align__(16) ushort_t g_A2h[128 * 512], g_A2l[128 * 512];  // hi/lo [row][k]
__device__ __align__(16) ushort_t g_A4h[512 * 128], g_A4l[512 * 128];  // hi/lo [row][k]
__device__ __align__(16) ushort_t g_T5[64 * 256];           // single fp16 [k|32+k][w], UNSCALED

// ================= table init =================
__global__ void init_tables() {
    int t = blockIdx.x * 256 + threadIdx.x;   // 0..65535
    ushort_t h, l;
    if (t < 256 * 64) {     // T1 [w][c]: c<32 cos, c>=32 -sin  (single fp16)
        int w = t >> 6, c = t & 63, y = c & 31;
        int m = (w * y) & 255;
        double s, ct; sincospi(2.0 * m / 256.0, &s, &ct);
        g_T1[t] = h1((c < 32) ? (float)ct : (float)(-s));
    }
    {                       // A2 128x512 (hi/lo)
        int r = t >> 9, k = t & 511;
        int pk = k >> 8, hh = k & 255;
        int j = r & 63;
        int xr = (j < 32) ? j : (192 + j);
        int m = (xr * hh) & 255;
        double s, ct; sincospi(2.0 * m / 256.0, &s, &ct);
        float v;
        if (r < 64) v = (pk == 0) ? (float)ct : (float)s;
        else        v = (pk == 0) ? (float)(-s) : (float)ct;
        hsplit(v, h, l);
        g_A2h[t] = h; g_A2l[t] = l;
    }
    {                       // A4 512x128 (hi/lo)
        int r = t >> 7, c = t & 127;
        int pr = r >> 8, hh = r & 255;
        int pc = c >> 6, j = c & 63;
        int xr = (j < 32) ? j : (192 + j);
        int m = (xr * hh) & 255;
        double s, ct; sincospi(2.0 * m / 256.0, &s, &ct);
        float v;
        if (pr == 0) v = (pc == 0) ? (float)ct : (float)(-s);
        else         v = (pc == 0) ? (float)s  : (float)ct;
        hsplit(v, h, l);
        g_A4h[t] = h; g_A4l[t] = l;
    }
    if (t < 64 * 256) {     // T5 [k|32+k][w], UNSCALED c_k; 1/65536 in S5 epilogue (single fp16)
        int r = t >> 8, w = t & 255, k = r & 31;
        int m = (k * w) & 255;
        double s, ct; sincospi(2.0 * m / 256.0, &s, &ct);
        double coef = (k == 0) ? 1.0 : 2.0;
        g_T5[t] = h1((r < 32) ? (float)(coef * ct) : (float)(-coef * s));
    }
}

// ================= double-buffered cp.async fp16 warp-MMA GEMM =================
// C(M x NTOT) = A(M x KDIM) * B(KDIM x NTOT).
// AMODE 0: A fp32 -> single fp16 in-kernel.  AMODE 1: A pre-split hi/lo (2 planes).
// AMODE 2: A single fp16 via cp.async.
// BPL: B smem planes (1 = single fp16, 2 = hi/lo pre-split).
// Passes per (a,b): APL==2 -> a0*b0 + a1*b0 ; BPL==2 -> a0*b0 + a0*b1 ; else a0*b0.
// CMODE 0: row-major f32.  CMODE 1: -> g_Y fp16 plane scatter (staged).
// CMODE 2: -> g_V fp16 emit.  CMODE 3: row-major f32 staged, scaled by 1/65536.
template<int BM, int BN, int BK, int WM, int WN, long KDIM, long NTOT,
         int AMODE, int BPL, int CMODE>
__global__ void __launch_bounds__(256, 2) mgemm(
    const float* __restrict__ Af, const ushort_t* __restrict__ Ahg,
    const ushort_t* __restrict__ Alg,
    const ushort_t* __restrict__ Bhg, const ushort_t* __restrict__ Blg,
    float* __restrict__ Cf)
{
    constexpr int TWM = BM / WM, TWN = BN / WN, MT = TWM / 16, NT = TWN / 8;
    constexpr int APL = (AMODE == 1) ? 2 : 1;
    constexpr int BKP = BK + 8, BNP = BN + 8;
    constexpr int PA = BM * BKP * 2;            // bytes per A plane
    constexpr int PB = BK * BNP * 2;            // bytes per B plane
    constexpr int OA0 = 0, OA1 = PA;
    constexpr int OB0 = APL * PA, OB1 = OB0 + PB;
    constexpr int SBUF = APL * PA + BPL * PB;
    constexpr long KT = KDIM / BK;
    constexpr int NBUF = (KT > 1) ? 2 : 1;
    constexpr int AF4 = BM * BK / 1024;         // float4/thread (AMODE 0)
    constexpr int AF8 = BM * BK / 2048;         // 16B cp.async/thread per A plane
    constexpr int BF8 = BK * BN / 2048;
    static_assert(WM * WN == 8 && (NT % 2) == 0, "cfg");

    extern __shared__ char smem[];
    const uint32_t sb = smem_u32(smem);
    const int t = threadIdx.x, wid = t >> 5, lane = t & 31;
    const int wm = wid / WN, wn = wid % WN;
    const long rowBase = (long)blockIdx.x * BM;
    const long colBase = (long)blockIdx.y * BN;

    float4 aReg[AMODE == 0 ? AF4 : 1];
    float  acc[MT][NT][4];
#pragma unroll
    for (int i = 0; i < MT; ++i)
#pragma unroll
        for (int j = 0; j < NT; ++j)
#pragma unroll
            for (int q = 0; q < 4; ++q) acc[i][j][q] = 0.f;

    auto fetchAsync = [&](long k0, int buf) {
        const uint32_t bb = sb + buf * SBUF;
        if constexpr (AMODE == 1) {
#pragma unroll
            for (int f8 = 0; f8 < AF8; ++f8) {
                int f = t + f8 * 256;
                int ar = f / (BK / 8), ac8 = f % (BK / 8);
                uint32_t off = (uint32_t)(ar * BKP + ac8 * 8) * 2;
                cpa16(bb + OA0 + off, &Ahg[(rowBase + ar) * KDIM + k0 + ac8 * 8]);
                cpa16(bb + OA1 + off, &Alg[(rowBase + ar) * KDIM + k0 + ac8 * 8]);
            }
        } else if constexpr (AMODE == 2) {
#pragma unroll
            for (int f8 = 0; f8 < AF8; ++f8) {
                int f = t + f8 * 256;
                int ar = f / (BK / 8), ac8 = f % (BK / 8);
                uint32_t off = (uint32_t)(ar * BKP + ac8 * 8) * 2;
                cpa16(bb + OA0 + off, &Ahg[(rowBase + ar) * KDIM + k0 + ac8 * 8]);
            }
        }
#pragma unroll
        for (int f8 = 0; f8 < BF8; ++f8) {
            int f = t + f8 * 256;
            int br = f / (BN / 8), bc8 = f % (BN / 8);
            uint32_t off = (uint32_t)(br * BNP + bc8 * 8) * 2;
            cpa16(bb + OB0 + off, &Bhg[(k0 + br) * NTOT + colBase + bc8 * 8]);
            if constexpr (BPL == 2)
                cpa16(bb + OB1 + off, &Blg[(k0 + br) * NTOT + colBase + bc8 * 8]);
        }
    };
    auto loadA = [&](long k0) {   // AMODE 0 only
#pragma unroll
        for (int f4 = 0; f4 < AF4; ++f4) {
            int f = t + f4 * 256;
            int ar = f / (BK / 4), ac = f % (BK / 4);
            aReg[f4] = *reinterpret_cast<const float4*>(
                &Af[(rowBase + ar) * KDIM + k0 + ac * 4]);
        }
    };
    auto storeA = [&](int buf) {  // AMODE 0 only: single fp16
#pragma unroll
        for (int f4 = 0; f4 < AF4; ++f4) {
            int f = t + f4 * 256;
            int ar = f / (BK / 4), ac = f % (BK / 4);
            ushort_t q0 = h1(aReg[f4].x), q1 = h1(aReg[f4].y);
            ushort_t q2 = h1(aReg[f4].z), q3 = h1(aReg[f4].w);
            uint32_t off = buf * SBUF + (uint32_t)(ar * BKP + ac * 4) * 2;
            *reinterpret_cast<uint2*>(smem + OA0 + off) =
                make_uint2(q0 | ((uint32_t)q1 << 16), q2 | ((uint32_t)q3 << 16));
        }
    };
    auto compute = [&](int buf) {
        const uint32_t bb = sb + buf * SBUF;
#pragma unroll
        for (int ks = 0; ks < BK / 16; ++ks) {
            const int k0 = ks * 16;
            uint32_t a0[MT][4], a1[MT][4];
#pragma unroll
            for (int i = 0; i < MT; ++i) {
                int row = wm * TWM + i * 16 + (lane & 15);
                int col = k0 + ((lane >> 4) << 3);
                uint32_t off = (uint32_t)(row * BKP + col) * 2;
                ldm4(a0[i], bb + OA0 + off);
                if constexpr (APL == 2) ldm4(a1[i], bb + OA1 + off);
            }
#pragma unroll
            for (int pr = 0; pr < NT / 2; ++pr) {
                uint32_t b0[4], b1[4];
                int krow = k0 + ((lane >> 3) & 1) * 8 + (lane & 7);
                int coln = wn * TWN + (pr * 2 + (lane >> 4)) * 8;
                uint32_t boff = (uint32_t)(krow * BNP + coln) * 2;
                ldm4t(b0, bb + OB0 + boff);
                if constexpr (BPL == 2) ldm4t(b1, bb + OB1 + boff);
#pragma unroll
                for (int i = 0; i < MT; ++i)
#pragma unroll
                    for (int nn = 0; nn < 2; ++nn) {
                        float* c = acc[i][pr * 2 + nn];
                        mma16816(c, a0[i], b0 + nn * 2);
                        if constexpr (APL == 2) mma16816(c, a1[i], b0 + nn * 2);
                        else if constexpr (BPL == 2) mma16816(c, a0[i], b1 + nn * 2);
                    }
            }
        }
    };

    // prologue
    fetchAsync(0, 0);
    CPA_COMMIT();
    if constexpr (AMODE == 0) loadA(0);
    CPA_WAIT0();
    if constexpr (AMODE == 0) storeA(0);
    __syncthreads();

#pragma unroll 1
    for (long kt = 0; kt < KT; ++kt) {
        const int cur = (int)(kt % NBUF);
        const bool more = (kt + 1 < KT);
        if (more) {
            fetchAsync((kt + 1) * BK, cur ^ 1);
            CPA_COMMIT();
            if constexpr (AMODE == 0) loadA((kt + 1) * BK);
        }
        compute(cur);
        if (more) {
            if constexpr (AMODE == 0) storeA(cur ^ 1);
            CPA_WAIT0();
            __syncthreads();
        }
    }

    const int g = lane >> 2, tq = lane & 3;
    if constexpr (CMODE == 0) {
#pragma unroll
        for (int i = 0; i < MT; ++i)
#pragma unroll
            for (int j = 0; j < NT; ++j) {
                const float* c = acc[i][j];
                long r0 = rowBase + wm * TWM + i * 16 + g;
                long c0 = colBase + wn * TWN + j * 8 + tq * 2;
                *reinterpret_cast<float2*>(&Cf[r0 * NTOT + c0])       = make_float2(c[0], c[1]);
                *reinterpret_cast<float2*>(&Cf[(r0 + 8) * NTOT + c0]) = make_float2(c[2], c[3]);
            }
    } else if constexpr (CMODE == 2) {
#pragma unroll
        for (int i = 0; i < MT; ++i)
#pragma unroll
            for (int j = 0; j < NT; ++j) {
                const float* c = acc[i][j];
                long r0 = rowBase + wm * TWM + i * 16 + g;
                long c0 = colBase + wn * TWN + j * 8 + tq * 2;
                long pbc = c0 >> 5, y = c0 & 31;
#pragma unroll
                for (int rr = 0; rr < 2; ++rr) {
                    long r = r0 + rr * 8;
                    long plane = r >> 8, h = r & 255;
                    long addr = (pbc * 256 + h) * 64 + plane * 32 + y;
                    ushort_t q0 = h1(c[rr * 2]), q1 = h1(c[rr * 2 + 1]);
                    *reinterpret_cast<uint32_t*>(&g_V[addr]) = q0 | ((uint32_t)q1 << 16);
                }
            }
    } else {
        // staged: CMODE 1 (Y fp16 plane scatter) / CMODE 3 (f32 row-major scaled)
        float* stage = reinterpret_cast<float*>(smem);
        __syncthreads();
#pragma unroll
        for (int i = 0; i < MT; ++i)
#pragma unroll
            for (int j = 0; j < NT; ++j) {
                const float* c = acc[i][j];
                int row = wm * TWM + i * 16 + g;
                int col = wn * TWN + j * 8 + tq * 2;
                *reinterpret_cast<float2*>(&stage[row * (BN + 4) + col])       = make_float2(c[0], c[1]);
                *reinterpret_cast<float2*>(&stage[(row + 8) * (BN + 4) + col]) = make_float2(c[2], c[3]);
            }
        __syncthreads();
        if constexpr (CMODE == 1) {
            const long pbc = rowBase >> 8;
            const int hb = (int)(rowBase & 255);
#pragma unroll
            for (int it = 0; it < BM * BN / 1024; ++it) {
                int idx = t + it * 256;
                int r = idx / (BN / 4), c4 = idx % (BN / 4);
                float4 v = *reinterpret_cast<float4*>(&stage[r * (BN + 4) + c4 * 4]);
                int c = c4 * 4, plane = c >> 5, y = c & 31;
                ushort_t q0 = h1(v.x), q1 = h1(v.y), q2 = h1(v.z), q3 = h1(v.w);
                long addr = (long)(plane * 256 + hb + r) * 32768L + pbc * 32 + y;
                *reinterpret_cast<uint2*>(&g_Y[addr]) =
                    make_uint2(q0 | ((uint32_t)q1 << 16), q2 | ((uint32_t)q3 << 16));
            }
        } else {
#pragma unroll
            for (int it = 0; it < BM * BN / 1024; ++it) {
                int idx = t + it * 256;
                int r = idx / (BN / 4), c4 = idx % (BN / 4);
                float4 v = *reinterpret_cast<float4*>(&stage[r * (BN + 4) + c4 * 4]);
                constexpr float SC = 1.0f / 65536.0f;
                v.x *= SC; v.y *= SC; v.z *= SC; v.w *= SC;
                *reinterpret_cast<float4*>(&Cf[(rowBase + r) * NTOT + colBase + c4 * 4]) = v;
            }
        }
    }
}

// ================= channel mix (proven; reads g_Z, emits g_Z3 fp16) =================
__global__ void __launch_bounds__(256, 2) chanmix(const float* __restrict__ Z,
                                                  const float* __restrict__ w1re,
                                                  const float* __restrict__ w1im,
                                                  const float* __restrict__ w4re,
                                                  const float* __restrict__ w4im) {
    __shared__ float Zs[2][4][32][32];
    __shared__ float Ws[2][2][2][32][32];
    const int t = threadIdx.x;
    const int p = blockIdx.x >> 6;
    const int j = blockIdx.x & 63;
    const int x = j & 31;
    const float* wre = (j < 32) ? w1re : w4re;
    const float* wim = (j < 32) ? w1im : w4im;

#pragma unroll
    for (int pass = 0; pass < 8; ++pass) {
        int f = t + pass * 256;
        int plane = f >> 10;
        int rem = f & 1023;
        int bi = rem >> 3;
        int y4 = rem & 7;
        float4 v = *reinterpret_cast<const float4*>(
            &Z[(size_t)(plane * 64 + j) * 32768 + (size_t)(p * 128 + bi) * 32 + y4 * 4]);
        *reinterpret_cast<float4*>(&Zs[plane][bi >> 5][bi & 31][y4 * 4]) = v;
    }
    __syncthreads();

    const int og = t >> 7;
    const int t2 = t & 127;
    const int bb = (t2 >> 5) & 3;
    const int y  = t & 31;

    float zre[32], zim[32];
#pragma unroll
    for (int i = 0; i < 32; ++i) {
        zre[i] = Zs[0][bb][i][y];
        zim[i] = Zs[1][bb][i][y];
    }

    auto fetchW = [&](int o, int buf) {
#pragma unroll
        for (int pass = 0; pass < 4; ++pass) {
            int f = t2 + pass * 128;
            int plane = f >> 8;
            int i = (f >> 3) & 31;
            int seg = f & 7;
            const float* wp = plane ? wim : wre;
            const float* gp = &wp[((((size_t)(i * 32 + o)) * 8 + p) * 32 + x) * 32 + seg * 4];
            cpa16(smem_u32(&Ws[og][buf][plane][i][seg * 4]), gp);
        }
    };

    fetchW(og * 16, 0);
    CPA_COMMIT();
    CPA_WAIT0();
    __syncthreads();

#pragma unroll 1
    for (int ol = 0; ol < 16; ++ol) {
        const int o = og * 16 + ol;
        const bool more = (ol + 1 < 16);
        if (more) {
            fetchW(o + 1, (ol + 1) & 1);
            CPA_COMMIT();
        }
        const int buf = ol & 1;
        float accre = 0.f, accim = 0.f;
#pragma unroll
        for (int i = 0; i < 32; ++i) {
            float wr = Ws[og][buf][0][i][y];
            float wi = Ws[og][buf][1][i][y];
            accre += zre[i] * wr - zim[i] * wi;
            accim += zre[i] * wi + zim[i] * wr;
        }
        size_t col = (size_t)(p * 128 + bb * 32 + o) * 32 + y;
        g_Z3[(size_t)j * 32768 + col]        = h1(accre);
        g_Z3[(size_t)(64 + j) * 32768 + col] = h1(accim);
        if (more) {
            CPA_WAIT0();
            __syncthreads();
        }
    }
}

// ================= launch =================
extern "C" void kernel_launch(void* const* d_in, const int* in_sizes, int n_in,
                              void* d_out, int out_size) {
    const float* x    = (const float*)d_in[0];
    const float* w1re = (const float*)d_in[1];
    const float* w1im = (const float*)d_in[2];
    const float* w4re = (const float*)d_in[3];
    const float* w4im = (const float*)d_in[4];
    float* out = (float*)d_out;

    void *pY, *pZ, *pZ3, *pV;
    void *pT1, *pA2h, *pA2l, *pA4h, *pA4l, *pT5;
    cudaGetSymbolAddress(&pY,   g_Y);
    cudaGetSymbolAddress(&pZ,   g_Z);
    cudaGetSymbolAddress(&pZ3,  g_Z3);
    cudaGetSymbolAddress(&pV,   g_V);
    cudaGetSymbolAddress(&pT1,  g_T1);
    cudaGetSymbolAddress(&pA2h, g_A2h);
    cudaGetSymbolAddress(&pA2l, g_A2l);
    cudaGetSymbolAddress(&pA4h, g_A4h);
    cudaGetSymbolAddress(&pA4l, g_A4l);
    cudaGetSymbolAddress(&pT5,  g_T5);

    // S1: A = x fp32 -> fp16; B = T1 single fp16 (1 MMA pass).  SBUF = 18432+9216, x2 buf
    auto s1k = mgemm<128, 64, 64, 4, 2, 256L, 64L, 0, 1, 1>;
    // S2: A = A2 hi/lo; B = Y single (2 passes).  SBUF = 2*18432+9216, x2
    auto s2k = mgemm<128, 64, 64, 4, 2, 512L, 32768L, 1, 1, 0>;
    // S4: A = A4 hi/lo; B = Z3 single (2 passes).
    auto s4k = mgemm<128, 64, 64, 4, 2, 128L, 32768L, 1, 1, 2>;
    // S5: A = V single fp16; B = T5 single fp16 (1 pass).  SBUF = 9216+17408; stage 33792
    auto s5k = mgemm<64, 128, 64, 2, 4, 64L, 256L, 2, 1, 3>;
    cudaFuncSetAttribute(s1k, cudaFuncAttributeMaxDynamicSharedMemorySize, 55296);
    cudaFuncSetAttribute(s2k, cudaFuncAttributeMaxDynamicSharedMemorySize, 92160);
    cudaFuncSetAttribute(s4k, cudaFuncAttributeMaxDynamicSharedMemorySize, 92160);
    cudaFuncSetAttribute(s5k, cudaFuncAttributeMaxDynamicSharedMemorySize, 34816);

    init_tables<<<256, 256>>>();

    // S1: Y(262144x64) = x(262144x256) * T1(256x64) -> Y fp16 plane scatter
    s1k<<<dim3(2048, 1), 256, 55296>>>(x, nullptr, nullptr,
                                       (const ushort_t*)pT1, nullptr, nullptr);

    // S2: Z(128x32768) = A2(128x512) * Y(512x32768) -> fp32
    s2k<<<dim3(1, 512), 256, 92160>>>(nullptr, (const ushort_t*)pA2h, (const ushort_t*)pA2l,
                                      (const ushort_t*)pY, nullptr, (float*)pZ);

    // S3: channel mixing (emits Z3 fp16)
    chanmix<<<512, 256>>>((const float*)pZ, w1re, w1im, w4re, w4im);

    // S4: V(512x32768) = A4(512x128) * Z3(128x32768) -> g_V fp16
    s4k<<<dim3(4, 512), 256, 92160>>>(nullptr, (const ushort_t*)pA4h, (const ushort_t*)pA4l,
                                      (const ushort_t*)pZ3, nullptr, nullptr);

    // S5: out(262144x256) = V(262144x64) * T5(64x256), scaled 1/65536 in epilogue
    s5k<<<dim3(4096, 2), 256, 34816>>>(nullptr, (const ushort_t*)pV, nullptr,
                                       (const ushort_t*)pT5, nullptr, out);
}

// round 14
// speedup vs baseline: 1.2643x; 1.0562x over previous
#include <cuda_runtime.h>
#include <cuda_fp16.h>
#include <cstdint>

// P=8, B=4, C=32, H=256, W=256, M1=M2=32
// rows R = P*B*C*H = 262144 ; pbc = P*B*C = 1024 ; cols (pbc,y) = 32768

typedef unsigned short ushort_t;

// ================= helpers =================
__device__ __forceinline__ uint32_t smem_u32(const void* p) {
    uint32_t a;
    asm("{ .reg .u64 t; cvta.to.shared.u64 t, %1; cvt.u32.u64 %0, t; }" : "=r"(a) : "l"(p));
    return a;
}
__device__ __forceinline__ void ldm4(uint32_t* r, uint32_t a) {
    asm volatile("ldmatrix.sync.aligned.m8n8.x4.shared.b16 {%0,%1,%2,%3}, [%4];"
                 : "=r"(r[0]), "=r"(r[1]), "=r"(r[2]), "=r"(r[3]) : "r"(a));
}
__device__ __forceinline__ void ldm4t(uint32_t* r, uint32_t a) {
    asm volatile("ldmatrix.sync.aligned.m8n8.x4.trans.shared.b16 {%0,%1,%2,%3}, [%4];"
                 : "=r"(r[0]), "=r"(r[1]), "=r"(r[2]), "=r"(r[3]) : "r"(a));
}
__device__ __forceinline__ void mma16816(float* c, const uint32_t* a, const uint32_t* b) {
    asm volatile("mma.sync.aligned.m16n8k16.row.col.f32.f16.f16.f32 "
                 "{%0,%1,%2,%3}, {%4,%5,%6,%7}, {%8,%9}, {%0,%1,%2,%3};"
                 : "+f"(c[0]), "+f"(c[1]), "+f"(c[2]), "+f"(c[3])
                 : "r"(a[0]), "r"(a[1]), "r"(a[2]), "r"(a[3]), "r"(b[0]), "r"(b[1]));
}
__device__ __forceinline__ ushort_t h1(float v) {
    return __half_as_ushort(__float2half_rn(v));
}
__device__ __forceinline__ void cpa16(uint32_t saddr, const void* g) {
    asm volatile("cp.async.cg.shared.global [%0], [%1], 16;" :: "r"(saddr), "l"(g));
}
#define CPA_COMMIT() asm volatile("cp.async.commit_group;" ::: "memory")
#define CPA_WAIT0()  asm volatile("cp.async.wait_group 0;" ::: "memory")

// ================= scratch =================
__device__ __align__(16) ushort_t g_Y [512u * 32768];       // fp16 [plane*256+h][pbc*32+y]
__device__ __align__(16) float    g_Z [128u * 32768];       // fp32 [plane*64+j][col]
__device__ __align__(16) ushort_t g_Z3[128u * 32768];       // fp16
__device__ __align__(16) ushort_t g_V [262144u * 64];       // fp16 [row][plane*32+y]
__device__ __align__(16) ushort_t g_T1[256 * 64];           // single fp16 [k=w][n]
__device__ __align__(16) ushort_t g_A2[128 * 512];          // single fp16 [row][k]
__device__ __align__(16) ushort_t g_A4[512 * 128];          // single fp16 [row][k]
__device__ __align__(16) ushort_t g_T5[64 * 256];           // single fp16 [k|32+k][w], UNSCALED

// ================= table init (all single RN fp16) =================
__global__ void init_tables() {
    int t = blockIdx.x * 256 + threadIdx.x;   // 0..65535
    if (t < 256 * 64) {     // T1 [w][c]: c<32 cos, c>=32 -sin
        int w = t >> 6, c = t & 63, y = c & 31;
        int m = (w * y) & 255;
        double s, ct; sincospi(2.0 * m / 256.0, &s, &ct);
        g_T1[t] = h1((c < 32) ? (float)ct : (float)(-s));
    }
    {                       // A2 128x512
        int r = t >> 9, k = t & 511;
        int pk = k >> 8, hh = k & 255;
        int j = r & 63;
        int xr = (j < 32) ? j : (192 + j);
        int m = (xr * hh) & 255;
        double s, ct; sincospi(2.0 * m / 256.0, &s, &ct);
        float v;
        if (r < 64) v = (pk == 0) ? (float)ct : (float)s;
        else        v = (pk == 0) ? (float)(-s) : (float)ct;
        g_A2[t] = h1(v);
    }
    {                       // A4 512x128
        int r = t >> 7, c = t & 127;
        int pr = r >> 8, hh = r & 255;
        int pc = c >> 6, j = c & 63;
        int xr = (j < 32) ? j : (192 + j);
        int m = (xr * hh) & 255;
        double s, ct; sincospi(2.0 * m / 256.0, &s, &ct);
        float v;
        if (pr == 0) v = (pc == 0) ? (float)ct : (float)(-s);
        else         v = (pc == 0) ? (float)s  : (float)ct;
        g_A4[t] = h1(v);
    }
    if (t < 64 * 256) {     // T5 [k|32+k][w], UNSCALED c_k; 1/65536 in S5 epilogue
        int r = t >> 8, w = t & 255, k = r & 31;
        int m = (k * w) & 255;
        double s, ct; sincospi(2.0 * m / 256.0, &s, &ct);
        double coef = (k == 0) ? 1.0 : 2.0;
        g_T5[t] = h1((r < 32) ? (float)(coef * ct) : (float)(-coef * s));
    }
}

// ================= double-buffered cp.async fp16 single-pass warp-MMA GEMM =================
// C(M x NTOT) = A(M x KDIM) * B(KDIM x NTOT). One MMA pass (all operands single fp16).
// AMODE 0: A fp32 -> single fp16 in-kernel.  AMODE 2: A single fp16 via cp.async.
// CMODE 0: row-major f32.  CMODE 1: -> g_Y fp16 plane scatter (staged).
// CMODE 2: -> g_V fp16 emit.  CMODE 3: row-major f32 staged, scaled by 1/65536.
template<int BM, int BN, int BK, int WM, int WN, long KDIM, long NTOT,
         int AMODE, int CMODE>
__global__ void __launch_bounds__(256, 2) mgemm(
    const float* __restrict__ Af, const ushort_t* __restrict__ Ahg,
    const ushort_t* __restrict__ Bhg, float* __restrict__ Cf)
{
    constexpr int TWM = BM / WM, TWN = BN / WN, MT = TWM / 16, NT = TWN / 8;
    constexpr int BKP = BK + 8, BNP = BN + 8;
    constexpr int PA = BM * BKP * 2;            // bytes per A plane
    constexpr int PB = BK * BNP * 2;            // bytes per B plane
    constexpr int OB0 = PA;
    constexpr int SBUF = PA + PB;
    constexpr long KT = KDIM / BK;
    constexpr int NBUF = (KT > 1) ? 2 : 1;
    constexpr int AF4 = BM * BK / 1024;         // float4/thread (AMODE 0)
    constexpr int AF8 = BM * BK / 2048;         // 16B cp.async/thread for A
    constexpr int BF8 = BK * BN / 2048;
    static_assert(WM * WN == 8 && (NT % 2) == 0, "cfg");

    extern __shared__ char smem[];
    const uint32_t sb = smem_u32(smem);
    const int t = threadIdx.x, wid = t >> 5, lane = t & 31;
    const int wm = wid / WN, wn = wid % WN;
    const long rowBase = (long)blockIdx.x * BM;
    const long colBase = (long)blockIdx.y * BN;

    float4 aReg[AMODE == 0 ? AF4 : 1];
    float  acc[MT][NT][4];
#pragma unroll
    for (int i = 0; i < MT; ++i)
#pragma unroll
        for (int j = 0; j < NT; ++j)
#pragma unroll
            for (int q = 0; q < 4; ++q) acc[i][j][q] = 0.f;

    auto fetchAsync = [&](long k0, int buf) {
        const uint32_t bb = sb + buf * SBUF;
        if constexpr (AMODE == 2) {
#pragma unroll
            for (int f8 = 0; f8 < AF8; ++f8) {
                int f = t + f8 * 256;
                int ar = f / (BK / 8), ac8 = f % (BK / 8);
                uint32_t off = (uint32_t)(ar * BKP + ac8 * 8) * 2;
                cpa16(bb + off, &Ahg[(rowBase + ar) * KDIM + k0 + ac8 * 8]);
            }
        }
#pragma unroll
        for (int f8 = 0; f8 < BF8; ++f8) {
            int f = t + f8 * 256;
            int br = f / (BN / 8), bc8 = f % (BN / 8);
            uint32_t off = (uint32_t)(br * BNP + bc8 * 8) * 2;
            cpa16(bb + OB0 + off, &Bhg[(k0 + br) * NTOT + colBase + bc8 * 8]);
        }
    };
    auto loadA = [&](long k0) {   // AMODE 0 only
#pragma unroll
        for (int f4 = 0; f4 < AF4; ++f4) {
            int f = t + f4 * 256;
            int ar = f / (BK / 4), ac = f % (BK / 4);
            aReg[f4] = *reinterpret_cast<const float4*>(
                &Af[(rowBase + ar) * KDIM + k0 + ac * 4]);
        }
    };
    auto storeA = [&](int buf) {  // AMODE 0 only
#pragma unroll
        for (int f4 = 0; f4 < AF4; ++f4) {
            int f = t + f4 * 256;
            int ar = f / (BK / 4), ac = f % (BK / 4);
            ushort_t q0 = h1(aReg[f4].x), q1 = h1(aReg[f4].y);
            ushort_t q2 = h1(aReg[f4].z), q3 = h1(aReg[f4].w);
            uint32_t off = buf * SBUF + (uint32_t)(ar * BKP + ac * 4) * 2;
            *reinterpret_cast<uint2*>(smem + off) =
                make_uint2(q0 | ((uint32_t)q1 << 16), q2 | ((uint32_t)q3 << 16));
        }
    };
    auto compute = [&](int buf) {
        const uint32_t bb = sb + buf * SBUF;
#pragma unroll
        for (int ks = 0; ks < BK / 16; ++ks) {
            const int k0 = ks * 16;
            uint32_t a0[MT][4];
#pragma unroll
            for (int i = 0; i < MT; ++i) {
                int row = wm * TWM + i * 16 + (lane & 15);
                int col = k0 + ((lane >> 4) << 3);
                ldm4(a0[i], bb + (uint32_t)(row * BKP + col) * 2);
            }
#pragma unroll
            for (int pr = 0; pr < NT / 2; ++pr) {
                uint32_t b0[4];
                int krow = k0 + ((lane >> 3) & 1) * 8 + (lane & 7);
                int coln = wn * TWN + (pr * 2 + (lane >> 4)) * 8;
                ldm4t(b0, bb + OB0 + (uint32_t)(krow * BNP + coln) * 2);
#pragma unroll
                for (int i = 0; i < MT; ++i)
#pragma unroll
                    for (int nn = 0; nn < 2; ++nn)
                        mma16816(acc[i][pr * 2 + nn], a0[i], b0 + nn * 2);
            }
        }
    };

    // prologue
    fetchAsync(0, 0);
    CPA_COMMIT();
    if constexpr (AMODE == 0) loadA(0);
    CPA_WAIT0();
    if constexpr (AMODE == 0) storeA(0);
    __syncthreads();

#pragma unroll 1
    for (long kt = 0; kt < KT; ++kt) {
        const int cur = (int)(kt % NBUF);
        const bool more = (kt + 1 < KT);
        if (more) {
            fetchAsync((kt + 1) * BK, cur ^ 1);
            CPA_COMMIT();
            if constexpr (AMODE == 0) loadA((kt + 1) * BK);
        }
        compute(cur);
        if (more) {
            if constexpr (AMODE == 0) storeA(cur ^ 1);
            CPA_WAIT0();
            __syncthreads();
        }
    }

    const int g = lane >> 2, tq = lane & 3;
    if constexpr (CMODE == 0) {
#pragma unroll
        for (int i = 0; i < MT; ++i)
#pragma unroll
            for (int j = 0; j < NT; ++j) {
                const float* c = acc[i][j];
                long r0 = rowBase + wm * TWM + i * 16 + g;
                long c0 = colBase + wn * TWN + j * 8 + tq * 2;
                *reinterpret_cast<float2*>(&Cf[r0 * NTOT + c0])       = make_float2(c[0], c[1]);
                *reinterpret_cast<float2*>(&Cf[(r0 + 8) * NTOT + c0]) = make_float2(c[2], c[3]);
            }
    } else if constexpr (CMODE == 2) {
#pragma unroll
        for (int i = 0; i < MT; ++i)
#pragma unroll
            for (int j = 0; j < NT; ++j) {
                const float* c = acc[i][j];
                long r0 = rowBase + wm * TWM + i * 16 + g;
                long c0 = colBase + wn * TWN + j * 8 + tq * 2;
                long pbc = c0 >> 5, y = c0 & 31;
#pragma unroll
                for (int rr = 0; rr < 2; ++rr) {
                    long r = r0 + rr * 8;
                    long plane = r >> 8, h = r & 255;
                    long addr = (pbc * 256 + h) * 64 + plane * 32 + y;
                    ushort_t q0 = h1(c[rr * 2]), q1 = h1(c[rr * 2 + 1]);
                    *reinterpret_cast<uint32_t*>(&g_V[addr]) = q0 | ((uint32_t)q1 << 16);
                }
            }
    } else {
        // staged: CMODE 1 (Y fp16 plane scatter) / CMODE 3 (f32 row-major scaled)
        float* stage = reinterpret_cast<float*>(smem);
        __syncthreads();
#pragma unroll
        for (int i = 0; i < MT; ++i)
#pragma unroll
            for (int j = 0; j < NT; ++j) {
                const float* c = acc[i][j];
                int row = wm * TWM + i * 16 + g;
                int col = wn * TWN + j * 8 + tq * 2;
                *reinterpret_cast<float2*>(&stage[row * (BN + 4) + col])       = make_float2(c[0], c[1]);
                *reinterpret_cast<float2*>(&stage[(row + 8) * (BN + 4) + col]) = make_float2(c[2], c[3]);
            }
        __syncthreads();
        if constexpr (CMODE == 1) {
            const long pbc = rowBase >> 8;
            const int hb = (int)(rowBase & 255);
#pragma unroll
            for (int it = 0; it < BM * BN / 1024; ++it) {
                int idx = t + it * 256;
                int r = idx / (BN / 4), c4 = idx % (BN / 4);
                float4 v = *reinterpret_cast<float4*>(&stage[r * (BN + 4) + c4 * 4]);
                int c = c4 * 4, plane = c >> 5, y = c & 31;
                ushort_t q0 = h1(v.x), q1 = h1(v.y), q2 = h1(v.z), q3 = h1(v.w);
                long addr = (long)(plane * 256 + hb + r) * 32768L + pbc * 32 + y;
                *reinterpret_cast<uint2*>(&g_Y[addr]) =
                    make_uint2(q0 | ((uint32_t)q1 << 16), q2 | ((uint32_t)q3 << 16));
            }
        } else {
#pragma unroll
            for (int it = 0; it < BM * BN / 1024; ++it) {
                int idx = t + it * 256;
                int r = idx / (BN / 4), c4 = idx % (BN / 4);
                float4 v = *reinterpret_cast<float4*>(&stage[r * (BN + 4) + c4 * 4]);
                constexpr float SC = 1.0f / 65536.0f;
                v.x *= SC; v.y *= SC; v.z *= SC; v.w *= SC;
                *reinterpret_cast<float4*>(&Cf[(rowBase + r) * NTOT + colBase + c4 * 4]) = v;
            }
        }
    }
}

// ================= channel mix (proven; reads g_Z, emits g_Z3 fp16) =================
__global__ void __launch_bounds__(256, 2) chanmix(const float* __restrict__ Z,
                                                  const float* __restrict__ w1re,
                                                  const float* __restrict__ w1im,
                                                  const float* __restrict__ w4re,
                                                  const float* __restrict__ w4im) {
    __shared__ float Zs[2][4][32][32];
    __shared__ float Ws[2][2][2][32][32];
    const int t = threadIdx.x;
    const int p = blockIdx.x >> 6;
    const int j = blockIdx.x & 63;
    const int x = j & 31;
    const float* wre = (j < 32) ? w1re : w4re;
    const float* wim = (j < 32) ? w1im : w4im;

#pragma unroll
    for (int pass = 0; pass < 8; ++pass) {
        int f = t + pass * 256;
        int plane = f >> 10;
        int rem = f & 1023;
        int bi = rem >> 3;
        int y4 = rem & 7;
        float4 v = *reinterpret_cast<const float4*>(
            &Z[(size_t)(plane * 64 + j) * 32768 + (size_t)(p * 128 + bi) * 32 + y4 * 4]);
        *reinterpret_cast<float4*>(&Zs[plane][bi >> 5][bi & 31][y4 * 4]) = v;
    }
    __syncthreads();

    const int og = t >> 7;
    const int t2 = t & 127;
    const int bb = (t2 >> 5) & 3;
    const int y  = t & 31;

    float zre[32], zim[32];
#pragma unroll
    for (int i = 0; i < 32; ++i) {
        zre[i] = Zs[0][bb][i][y];
        zim[i] = Zs[1][bb][i][y];
    }

    auto fetchW = [&](int o, int buf) {
#pragma unroll
        for (int pass = 0; pass < 4; ++pass) {
            int f = t2 + pass * 128;
            int plane = f >> 8;
            int i = (f >> 3) & 31;
            int seg = f & 7;
            const float* wp = plane ? wim : wre;
            const float* gp = &wp[((((size_t)(i * 32 + o)) * 8 + p) * 32 + x) * 32 + seg * 4];
            cpa16(smem_u32(&Ws[og][buf][plane][i][seg * 4]), gp);
        }
    };

    fetchW(og * 16, 0);
    CPA_COMMIT();
    CPA_WAIT0();
    __syncthreads();

#pragma unroll 1
    for (int ol = 0; ol < 16; ++ol) {
        const int o = og * 16 + ol;
        const bool more = (ol + 1 < 16);
        if (more) {
            fetchW(o + 1, (ol + 1) & 1);
            CPA_COMMIT();
        }
        const int buf = ol & 1;
        float accre = 0.f, accim = 0.f;
#pragma unroll
        for (int i = 0; i < 32; ++i) {
            float wr = Ws[og][buf][0][i][y];
            float wi = Ws[og][buf][1][i][y];
            accre += zre[i] * wr - zim[i] * wi;
            accim += zre[i] * wi + zim[i] * wr;
        }
        size_t col = (size_t)(p * 128 + bb * 32 + o) * 32 + y;
        g_Z3[(size_t)j * 32768 + col]        = h1(accre);
        g_Z3[(size_t)(64 + j) * 32768 + col] = h1(accim);
        if (more) {
            CPA_WAIT0();
            __syncthreads();
        }
    }
}

// ================= launch =================
extern "C" void kernel_launch(void* const* d_in, const int* in_sizes, int n_in,
                              void* d_out, int out_size) {
    const float* x    = (const float*)d_in[0];
    const float* w1re = (const float*)d_in[1];
    const float* w1im = (const float*)d_in[2];
    const float* w4re = (const float*)d_in[3];
    const float* w4im = (const float*)d_in[4];
    float* out = (float*)d_out;

    void *pY, *pZ, *pZ3, *pV, *pT1, *pA2, *pA4, *pT5;
    cudaGetSymbolAddress(&pY,  g_Y);
    cudaGetSymbolAddress(&pZ,  g_Z);
    cudaGetSymbolAddress(&pZ3, g_Z3);
    cudaGetSymbolAddress(&pV,  g_V);
    cudaGetSymbolAddress(&pT1, g_T1);
    cudaGetSymbolAddress(&pA2, g_A2);
    cudaGetSymbolAddress(&pA4, g_A4);
    cudaGetSymbolAddress(&pT5, g_T5);

    // S1: A = x fp32 -> fp16; B = T1 single (1 pass).  SBUF = 18432+9216, x2
    auto s1k = mgemm<128, 64, 64, 4, 2, 256L, 64L, 0, 1>;
    // S2: A = A2 single; B = Y single (1 pass).  SBUF = 27648, x2
    auto s2k = mgemm<128, 64, 64, 4, 2, 512L, 32768L, 2, 0>;
    // S4: A = A4 single; B = Z3 single (1 pass).
    auto s4k = mgemm<128, 64, 64, 4, 2, 128L, 32768L, 2, 2>;
    // S5: A = V single; B = T5 single (1 pass).  SBUF = 9216+17408; stage 33792
    auto s5k = mgemm<64, 128, 64, 2, 4, 64L, 256L, 2, 3>;
    cudaFuncSetAttribute(s1k, cudaFuncAttributeMaxDynamicSharedMemorySize, 55296);
    cudaFuncSetAttribute(s2k, cudaFuncAttributeMaxDynamicSharedMemorySize, 55296);
    cudaFuncSetAttribute(s4k, cudaFuncAttributeMaxDynamicSharedMemorySize, 55296);
    cudaFuncSetAttribute(s5k, cudaFuncAttributeMaxDynamicSharedMemorySize, 34816);

    init_tables<<<256, 256>>>();

    // S1: Y(262144x64) = x(262144x256) * T1(256x64) -> Y fp16 plane scatter
    s1k<<<dim3(2048, 1), 256, 55296>>>(x, nullptr, (const ushort_t*)pT1, nullptr);

    // S2: Z(128x32768) = A2(128x512) * Y(512x32768) -> fp32
    s2k<<<dim3(1, 512), 256, 55296>>>(nullptr, (const ushort_t*)pA2,
                                      (const ushort_t*)pY, (float*)pZ);

    // S3: channel mixing (emits Z3 fp16)
    chanmix<<<512, 256>>>((const float*)pZ, w1re, w1im, w4re, w4im);

    // S4: V(512x32768) = A4(512x128) * Z3(128x32768) -> g_V fp16
    s4k<<<dim3(4, 512), 256, 55296>>>(nullptr, (const ushort_t*)pA4,
                                      (const ushort_t*)pZ3, nullptr);

    // S5: out(262144x256) = V(262144x64) * T5(64x256), scaled 1/65536 in epilogue
    s5k<<<dim3(4096, 2), 256, 34816>>>(nullptr, (const ushort_t*)pV,
                                       (const ushort_t*)pT5, out);
}

// round 15
// speedup vs baseline: 1.3014x; 1.0293x over previous
#include <cuda_runtime.h>
#include <cuda_fp16.h>
#include <cstdint>

// P=8, B=4, C=32, H=256, W=256, M1=M2=32
// rows R = P*B*C*H = 262144 ; pbc = P*B*C = 1024 ; cols (pbc,y) = 32768

typedef unsigned short ushort_t;

// ================= helpers =================
__device__ __forceinline__ uint32_t smem_u32(const void* p) {
    uint32_t a;
    asm("{ .reg .u64 t; cvta.to.shared.u64 t, %1; cvt.u32.u64 %0, t; }" : "=r"(a) : "l"(p));
    return a;
}
__device__ __forceinline__ void ldm4(uint32_t* r, uint32_t a) {
    asm volatile("ldmatrix.sync.aligned.m8n8.x4.shared.b16 {%0,%1,%2,%3}, [%4];"
                 : "=r"(r[0]), "=r"(r[1]), "=r"(r[2]), "=r"(r[3]) : "r"(a));
}
__device__ __forceinline__ void ldm4t(uint32_t* r, uint32_t a) {
    asm volatile("ldmatrix.sync.aligned.m8n8.x4.trans.shared.b16 {%0,%1,%2,%3}, [%4];"
                 : "=r"(r[0]), "=r"(r[1]), "=r"(r[2]), "=r"(r[3]) : "r"(a));
}
__device__ __forceinline__ void mma16816(float* c, const uint32_t* a, const uint32_t* b) {
    asm volatile("mma.sync.aligned.m16n8k16.row.col.f32.f16.f16.f32 "
                 "{%0,%1,%2,%3}, {%4,%5,%6,%7}, {%8,%9}, {%0,%1,%2,%3};"
                 : "+f"(c[0]), "+f"(c[1]), "+f"(c[2]), "+f"(c[3])
                 : "r"(a[0]), "r"(a[1]), "r"(a[2]), "r"(a[3]), "r"(b[0]), "r"(b[1]));
}
__device__ __forceinline__ ushort_t h1(float v) {
    return __half_as_ushort(__float2half_rn(v));
}
__device__ __forceinline__ void cpa16(uint32_t saddr, const void* g) {
    asm volatile("cp.async.cg.shared.global [%0], [%1], 16;" :: "r"(saddr), "l"(g));
}
#define CPA_COMMIT() asm volatile("cp.async.commit_group;" ::: "memory")
#define CPA_WAIT0()  asm volatile("cp.async.wait_group 0;" ::: "memory")

// ================= scratch =================
__device__ __align__(16) ushort_t g_Y [512u * 32768];       // fp16 [plane*256+h][pbc*32+y]
__device__ __align__(16) ushort_t g_Z [128u * 32768];       // fp16 [plane*64+j][col]
__device__ __align__(16) ushort_t g_Z3[128u * 32768];       // fp16
__device__ __align__(16) ushort_t g_V [262144u * 64];       // fp16 [row][plane*32+y]
__device__ __align__(16) ushort_t g_T1[256 * 64];           // fp16 [k=w][n]
__device__ __align__(16) ushort_t g_A2[128 * 512];          // fp16 [row][k]
__device__ __align__(16) ushort_t g_A4[512 * 128];          // fp16 [row][k]
__device__ __align__(16) ushort_t g_T5[64 * 256];           // fp16 [k|32+k][w], UNSCALED

// ================= table init (all single RN fp16) =================
__global__ void init_tables() {
    int t = blockIdx.x * 256 + threadIdx.x;   // 0..65535
    if (t < 256 * 64) {     // T1 [w][c]: c<32 cos, c>=32 -sin
        int w = t >> 6, c = t & 63, y = c & 31;
        int m = (w * y) & 255;
        double s, ct; sincospi(2.0 * m / 256.0, &s, &ct);
        g_T1[t] = h1((c < 32) ? (float)ct : (float)(-s));
    }
    {                       // A2 128x512
        int r = t >> 9, k = t & 511;
        int pk = k >> 8, hh = k & 255;
        int j = r & 63;
        int xr = (j < 32) ? j : (192 + j);
        int m = (xr * hh) & 255;
        double s, ct; sincospi(2.0 * m / 256.0, &s, &ct);
        float v;
        if (r < 64) v = (pk == 0) ? (float)ct : (float)s;
        else        v = (pk == 0) ? (float)(-s) : (float)ct;
        g_A2[t] = h1(v);
    }
    {                       // A4 512x128
        int r = t >> 7, c = t & 127;
        int pr = r >> 8, hh = r & 255;
        int pc = c >> 6, j = c & 63;
        int xr = (j < 32) ? j : (192 + j);
        int m = (xr * hh) & 255;
        double s, ct; sincospi(2.0 * m / 256.0, &s, &ct);
        float v;
        if (pr == 0) v = (pc == 0) ? (float)ct : (float)(-s);
        else         v = (pc == 0) ? (float)s  : (float)ct;
        g_A4[t] = h1(v);
    }
    if (t < 64 * 256) {     // T5 [k|32+k][w], UNSCALED c_k; 1/65536 in S5 epilogue
        int r = t >> 8, w = t & 255, k = r & 31;
        int m = (k * w) & 255;
        double s, ct; sincospi(2.0 * m / 256.0, &s, &ct);
        double coef = (k == 0) ? 1.0 : 2.0;
        g_T5[t] = h1((r < 32) ? (float)(coef * ct) : (float)(-coef * s));
    }
}

// ================= double-buffered cp.async fp16 single-pass warp-MMA GEMM =================
// C(M x NTOT) = A(M x KDIM) * B(KDIM x NTOT). One MMA pass.
// AMODE 0: A fp32 -> fp16 in-kernel.  AMODE 2: A fp16 via cp.async.
// CMODE 1: -> g_Y fp16 plane scatter (staged).  CMODE 2: -> g_V fp16 emit.
// CMODE 3: row-major f32 staged, scaled by 1/65536.  CMODE 4: -> g_Z fp16 row-major emit.
// OCC: min blocks per SM for __launch_bounds__.
template<int BM, int BN, int BK, int WM, int WN, long KDIM, long NTOT,
         int AMODE, int CMODE, int OCC>
__global__ void __launch_bounds__(256, OCC) mgemm(
    const float* __restrict__ Af, const ushort_t* __restrict__ Ahg,
    const ushort_t* __restrict__ Bhg, float* __restrict__ Cf)
{
    constexpr int TWM = BM / WM, TWN = BN / WN, MT = TWM / 16, NT = TWN / 8;
    constexpr int BKP = BK + 8, BNP = BN + 8;
    constexpr int PA = BM * BKP * 2;            // bytes per A plane
    constexpr int PB = BK * BNP * 2;            // bytes per B plane
    constexpr int OB0 = PA;
    constexpr int SBUF = PA + PB;
    constexpr long KT = KDIM / BK;
    constexpr int NBUF = (KT > 1) ? 2 : 1;
    constexpr int AF4 = BM * BK / 1024;         // float4/thread (AMODE 0)
    constexpr int AF8 = BM * BK / 2048;         // 16B cp.async/thread for A
    constexpr int BF8 = BK * BN / 2048;
    static_assert(WM * WN == 8 && (NT % 2) == 0, "cfg");

    extern __shared__ char smem[];
    const uint32_t sb = smem_u32(smem);
    const int t = threadIdx.x, wid = t >> 5, lane = t & 31;
    const int wm = wid / WN, wn = wid % WN;
    const long rowBase = (long)blockIdx.x * BM;
    const long colBase = (long)blockIdx.y * BN;

    float4 aReg[AMODE == 0 ? AF4 : 1];
    float  acc[MT][NT][4];
#pragma unroll
    for (int i = 0; i < MT; ++i)
#pragma unroll
        for (int j = 0; j < NT; ++j)
#pragma unroll
            for (int q = 0; q < 4; ++q) acc[i][j][q] = 0.f;

    auto fetchAsync = [&](long k0, int buf) {
        const uint32_t bb = sb + buf * SBUF;
        if constexpr (AMODE == 2) {
#pragma unroll
            for (int f8 = 0; f8 < AF8; ++f8) {
                int f = t + f8 * 256;
                int ar = f / (BK / 8), ac8 = f % (BK / 8);
                uint32_t off = (uint32_t)(ar * BKP + ac8 * 8) * 2;
                cpa16(bb + off, &Ahg[(rowBase + ar) * KDIM + k0 + ac8 * 8]);
            }
        }
#pragma unroll
        for (int f8 = 0; f8 < BF8; ++f8) {
            int f = t + f8 * 256;
            int br = f / (BN / 8), bc8 = f % (BN / 8);
            uint32_t off = (uint32_t)(br * BNP + bc8 * 8) * 2;
            cpa16(bb + OB0 + off, &Bhg[(k0 + br) * NTOT + colBase + bc8 * 8]);
        }
    };
    auto loadA = [&](long k0) {   // AMODE 0 only
#pragma unroll
        for (int f4 = 0; f4 < AF4; ++f4) {
            int f = t + f4 * 256;
            int ar = f / (BK / 4), ac = f % (BK / 4);
            aReg[f4] = *reinterpret_cast<const float4*>(
                &Af[(rowBase + ar) * KDIM + k0 + ac * 4]);
        }
    };
    auto storeA = [&](int buf) {  // AMODE 0 only
#pragma unroll
        for (int f4 = 0; f4 < AF4; ++f4) {
            int f = t + f4 * 256;
            int ar = f / (BK / 4), ac = f % (BK / 4);
            ushort_t q0 = h1(aReg[f4].x), q1 = h1(aReg[f4].y);
            ushort_t q2 = h1(aReg[f4].z), q3 = h1(aReg[f4].w);
            uint32_t off = buf * SBUF + (uint32_t)(ar * BKP + ac * 4) * 2;
            *reinterpret_cast<uint2*>(smem + off) =
                make_uint2(q0 | ((uint32_t)q1 << 16), q2 | ((uint32_t)q3 << 16));
        }
    };
    auto compute = [&](int buf) {
        const uint32_t bb = sb + buf * SBUF;
#pragma unroll
        for (int ks = 0; ks < BK / 16; ++ks) {
            const int k0 = ks * 16;
            uint32_t a0[MT][4];
#pragma unroll
            for (int i = 0; i < MT; ++i) {
                int row = wm * TWM + i * 16 + (lane & 15);
                int col = k0 + ((lane >> 4) << 3);
                ldm4(a0[i], bb + (uint32_t)(row * BKP + col) * 2);
            }
#pragma unroll
            for (int pr = 0; pr < NT / 2; ++pr) {
                uint32_t b0[4];
                int krow = k0 + ((lane >> 3) & 1) * 8 + (lane & 7);
                int coln = wn * TWN + (pr * 2 + (lane >> 4)) * 8;
                ldm4t(b0, bb + OB0 + (uint32_t)(krow * BNP + coln) * 2);
#pragma unroll
                for (int i = 0; i < MT; ++i)
#pragma unroll
                    for (int nn = 0; nn < 2; ++nn)
                        mma16816(acc[i][pr * 2 + nn], a0[i], b0 + nn * 2);
            }
        }
    };

    // prologue
    fetchAsync(0, 0);
    CPA_COMMIT();
    if constexpr (AMODE == 0) loadA(0);
    CPA_WAIT0();
    if constexpr (AMODE == 0) storeA(0);
    __syncthreads();

#pragma unroll 1
    for (long kt = 0; kt < KT; ++kt) {
        const int cur = (int)(kt % NBUF);
        const bool more = (kt + 1 < KT);
        if (more) {
            fetchAsync((kt + 1) * BK, cur ^ 1);
            CPA_COMMIT();
            if constexpr (AMODE == 0) loadA((kt + 1) * BK);
        }
        compute(cur);
        if (more) {
            if constexpr (AMODE == 0) storeA(cur ^ 1);
            CPA_WAIT0();
            __syncthreads();
        }
    }

    const int g = lane >> 2, tq = lane & 3;
    if constexpr (CMODE == 4) {
#pragma unroll
        for (int i = 0; i < MT; ++i)
#pragma unroll
            for (int j = 0; j < NT; ++j) {
                const float* c = acc[i][j];
                long r0 = rowBase + wm * TWM + i * 16 + g;
                long c0 = colBase + wn * TWN + j * 8 + tq * 2;
#pragma unroll
                for (int rr = 0; rr < 2; ++rr) {
                    ushort_t q0 = h1(c[rr * 2]), q1 = h1(c[rr * 2 + 1]);
                    *reinterpret_cast<uint32_t*>(&g_Z[(r0 + rr * 8) * NTOT + c0]) =
                        q0 | ((uint32_t)q1 << 16);
                }
            }
    } else if constexpr (CMODE == 2) {
#pragma unroll
        for (int i = 0; i < MT; ++i)
#pragma unroll
            for (int j = 0; j < NT; ++j) {
                const float* c = acc[i][j];
                long r0 = rowBase + wm * TWM + i * 16 + g;
                long c0 = colBase + wn * TWN + j * 8 + tq * 2;
                long pbc = c0 >> 5, y = c0 & 31;
#pragma unroll
                for (int rr = 0; rr < 2; ++rr) {
                    long r = r0 + rr * 8;
                    long plane = r >> 8, h = r & 255;
                    long addr = (pbc * 256 + h) * 64 + plane * 32 + y;
                    ushort_t q0 = h1(c[rr * 2]), q1 = h1(c[rr * 2 + 1]);
                    *reinterpret_cast<uint32_t*>(&g_V[addr]) = q0 | ((uint32_t)q1 << 16);
                }
            }
    } else {
        // staged: CMODE 1 (Y fp16 plane scatter) / CMODE 3 (f32 row-major scaled)
        float* stage = reinterpret_cast<float*>(smem);
        __syncthreads();
#pragma unroll
        for (int i = 0; i < MT; ++i)
#pragma unroll
            for (int j = 0; j < NT; ++j) {
                const float* c = acc[i][j];
                int row = wm * TWM + i * 16 + g;
                int col = wn * TWN + j * 8 + tq * 2;
                *reinterpret_cast<float2*>(&stage[row * (BN + 4) + col])       = make_float2(c[0], c[1]);
                *reinterpret_cast<float2*>(&stage[(row + 8) * (BN + 4) + col]) = make_float2(c[2], c[3]);
            }
        __syncthreads();
        if constexpr (CMODE == 1) {
            const long pbc = rowBase >> 8;
            const int hb = (int)(rowBase & 255);
#pragma unroll
            for (int it = 0; it < BM * BN / 1024; ++it) {
                int idx = t + it * 256;
                int r = idx / (BN / 4), c4 = idx % (BN / 4);
                float4 v = *reinterpret_cast<float4*>(&stage[r * (BN + 4) + c4 * 4]);
                int c = c4 * 4, plane = c >> 5, y = c & 31;
                ushort_t q0 = h1(v.x), q1 = h1(v.y), q2 = h1(v.z), q3 = h1(v.w);
                long addr = (long)(plane * 256 + hb + r) * 32768L + pbc * 32 + y;
                *reinterpret_cast<uint2*>(&g_Y[addr]) =
                    make_uint2(q0 | ((uint32_t)q1 << 16), q2 | ((uint32_t)q3 << 16));
            }
        } else {
#pragma unroll
            for (int it = 0; it < BM * BN / 1024; ++it) {
                int idx = t + it * 256;
                int r = idx / (BN / 4), c4 = idx % (BN / 4);
                float4 v = *reinterpret_cast<float4*>(&stage[r * (BN + 4) + c4 * 4]);
                constexpr float SC = 1.0f / 65536.0f;
                v.x *= SC; v.y *= SC; v.z *= SC; v.w *= SC;
                *reinterpret_cast<float4*>(&Cf[(rowBase + r) * NTOT + colBase + c4 * 4]) = v;
            }
        }
    }
}

// ================= channel mix: Z fp16, half2 reg cache, 3 CTAs/SM =================
__global__ void __launch_bounds__(256, 3) chanmix(const ushort_t* __restrict__ Z,
                                                  const float* __restrict__ w1re,
                                                  const float* __restrict__ w1im,
                                                  const float* __restrict__ w4re,
                                                  const float* __restrict__ w4im) {
    __shared__ ushort_t Zs[2][128][32];       // [plane][b*32+i][y] 16 KB
    __shared__ float Ws[2][2][2][32][32];     // [grp][buf][plane][i][y] 32 KB
    const int t = threadIdx.x;
    const int p = blockIdx.x >> 6;
    const int j = blockIdx.x & 63;
    const int x = j & 31;
    const float* wre = (j < 32) ? w1re : w4re;
    const float* wim = (j < 32) ? w1im : w4im;

    // load Z tile (fp16): 2 planes x 128 bi x 32 y = 8192 halves = 1024 uint4
#pragma unroll
    for (int pass = 0; pass < 4; ++pass) {
        int f = t + pass * 256;
        int plane = f >> 9;
        int rem = f & 511;
        int bi = rem >> 2;          // 0..127
        int y8 = rem & 3;           // 8 halves each
        uint4 v = *reinterpret_cast<const uint4*>(
            &Z[(size_t)(plane * 64 + j) * 32768 + (size_t)(p * 128 + bi) * 32 + y8 * 8]);
        *reinterpret_cast<uint4*>(&Zs[plane][bi][y8 * 8]) = v;
    }
    __syncthreads();

    const int og = t >> 7;
    const int t2 = t & 127;
    const int bb = (t2 >> 5) & 3;
    const int y  = t & 31;

    // register cache: (zre, zim) packed per i
    __half2 zri[32];
#pragma unroll
    for (int i = 0; i < 32; ++i) {
        __half zr = __ushort_as_half(Zs[0][bb * 32 + i][y]);
        __half zi = __ushort_as_half(Zs[1][bb * 32 + i][y]);
        zri[i] = __halves2half2(zr, zi);
    }

    auto fetchW = [&](int o, int buf) {
#pragma unroll
        for (int pass = 0; pass < 4; ++pass) {
            int f = t2 + pass * 128;
            int plane = f >> 8;
            int i = (f >> 3) & 31;
            int seg = f & 7;
            const float* wp = plane ? wim : wre;
            const float* gp = &wp[((((size_t)(i * 32 + o)) * 8 + p) * 32 + x) * 32 + seg * 4];
            cpa16(smem_u32(&Ws[og][buf][plane][i][seg * 4]), gp);
        }
    };

    fetchW(og * 16, 0);
    CPA_COMMIT();
    CPA_WAIT0();
    __syncthreads();

#pragma unroll 1
    for (int ol = 0; ol < 16; ++ol) {
        const int o = og * 16 + ol;
        const bool more = (ol + 1 < 16);
        if (more) {
            fetchW(o + 1, (ol + 1) & 1);
            CPA_COMMIT();
        }
        const int buf = ol & 1;
        float accre = 0.f, accim = 0.f;
#pragma unroll
        for (int i = 0; i < 32; ++i) {
            float2 z = __half22float2(zri[i]);
            float wr = Ws[og][buf][0][i][y];
            float wi = Ws[og][buf][1][i][y];
            accre += z.x * wr - z.y * wi;
            accim += z.x * wi + z.y * wr;
        }
        size_t col = (size_t)(p * 128 + bb * 32 + o) * 32 + y;
        g_Z3[(size_t)j * 32768 + col]        = h1(accre);
        g_Z3[(size_t)(64 + j) * 32768 + col] = h1(accim);
        if (more) {
            CPA_WAIT0();
            __syncthreads();
        }
    }
}

// ================= launch =================
extern "C" void kernel_launch(void* const* d_in, const int* in_sizes, int n_in,
                              void* d_out, int out_size) {
    const float* x    = (const float*)d_in[0];
    const float* w1re = (const float*)d_in[1];
    const float* w1im = (const float*)d_in[2];
    const float* w4re = (const float*)d_in[3];
    const float* w4im = (const float*)d_in[4];
    float* out = (float*)d_out;

    void *pY, *pZ, *pZ3, *pV, *pT1, *pA2, *pA4, *pT5;
    cudaGetSymbolAddress(&pY,  g_Y);
    cudaGetSymbolAddress(&pZ,  g_Z);
    cudaGetSymbolAddress(&pZ3, g_Z3);
    cudaGetSymbolAddress(&pV,  g_V);
    cudaGetSymbolAddress(&pT1, g_T1);
    cudaGetSymbolAddress(&pA2, g_A2);
    cudaGetSymbolAddress(&pA4, g_A4);
    cudaGetSymbolAddress(&pT5, g_T5);

    // S1: A = x fp32 -> fp16; B = T1 (1 pass).  SBUF = 27648, x2 buf
    auto s1k = mgemm<128, 64, 64, 4, 2, 256L, 64L, 0, 1, 2>;
    // S2: A = A2; B = Y (1 pass) -> g_Z fp16.  SBUF = 27648, x2
    auto s2k = mgemm<128, 64, 64, 4, 2, 512L, 32768L, 2, 4, 2>;
    // S4: A = A4; B = Z3 (1 pass) -> g_V fp16.
    auto s4k = mgemm<128, 64, 64, 4, 2, 128L, 32768L, 2, 2, 2>;
    // S5: A = V; B = T5 (1 pass) -> out f32 staged/scaled.  SBUF = 26624; stage 33792
    auto s5k = mgemm<64, 128, 64, 2, 4, 64L, 256L, 2, 3, 3>;
    cudaFuncSetAttribute(s1k, cudaFuncAttributeMaxDynamicSharedMemorySize, 55296);
    cudaFuncSetAttribute(s2k, cudaFuncAttributeMaxDynamicSharedMemorySize, 55296);
    cudaFuncSetAttribute(s4k, cudaFuncAttributeMaxDynamicSharedMemorySize, 55296);
    cudaFuncSetAttribute(s5k, cudaFuncAttributeMaxDynamicSharedMemorySize, 34816);

    init_tables<<<256, 256>>>();

    // S1: Y(262144x64) = x(262144x256) * T1(256x64) -> Y fp16 plane scatter
    s1k<<<dim3(2048, 1), 256, 55296>>>(x, nullptr, (const ushort_t*)pT1, nullptr);

    // S2: Z(128x32768) = A2(128x512) * Y(512x32768) -> g_Z fp16
    s2k<<<dim3(1, 512), 256, 55296>>>(nullptr, (const ushort_t*)pA2,
                                      (const ushort_t*)pY, nullptr);

    // S3: channel mixing (reads Z fp16, emits Z3 fp16)
    chanmix<<<512, 256>>>((const ushort_t*)pZ, w1re, w1im, w4re, w4im);

    // S4: V(512x32768) = A4(512x128) * Z3(128x32768) -> g_V fp16
    s4k<<<dim3(4, 512), 256, 55296>>>(nullptr, (const ushort_t*)pA4,
                                      (const ushort_t*)pZ3, nullptr);

    // S5: out(262144x256) = V(262144x64) * T5(64x256), scaled 1/65536 in epilogue
    s5k<<<dim3(4096, 2), 256, 34816>>>(nullptr, (const ushort_t*)pV,
                                       (const ushort_t*)pT5, out);
}

// round 16
// speedup vs baseline: 1.3445x; 1.0331x over previous
#include <cuda_runtime.h>
#include <cuda_fp16.h>
#include <cstdint>

// P=8, B=4, C=32, H=256, W=256, M1=M2=32
// rows R = P*B*C*H = 262144 ; pbc = P*B*C = 1024 ; cols (pbc,y) = 32768

typedef unsigned short ushort_t;

// ================= helpers =================
__device__ __forceinline__ uint32_t smem_u32(const void* p) {
    uint32_t a;
    asm("{ .reg .u64 t; cvta.to.shared.u64 t, %1; cvt.u32.u64 %0, t; }" : "=r"(a) : "l"(p));
    return a;
}
__device__ __forceinline__ void ldm4(uint32_t* r, uint32_t a) {
    asm volatile("ldmatrix.sync.aligned.m8n8.x4.shared.b16 {%0,%1,%2,%3}, [%4];"
                 : "=r"(r[0]), "=r"(r[1]), "=r"(r[2]), "=r"(r[3]) : "r"(a));
}
__device__ __forceinline__ void ldm4t(uint32_t* r, uint32_t a) {
    asm volatile("ldmatrix.sync.aligned.m8n8.x4.trans.shared.b16 {%0,%1,%2,%3}, [%4];"
                 : "=r"(r[0]), "=r"(r[1]), "=r"(r[2]), "=r"(r[3]) : "r"(a));
}
__device__ __forceinline__ void mma16816(float* c, const uint32_t* a, const uint32_t* b) {
    asm volatile("mma.sync.aligned.m16n8k16.row.col.f32.f16.f16.f32 "
                 "{%0,%1,%2,%3}, {%4,%5,%6,%7}, {%8,%9}, {%0,%1,%2,%3};"
                 : "+f"(c[0]), "+f"(c[1]), "+f"(c[2]), "+f"(c[3])
                 : "r"(a[0]), "r"(a[1]), "r"(a[2]), "r"(a[3]), "r"(b[0]), "r"(b[1]));
}
__device__ __forceinline__ ushort_t h1(float v) {
    return __half_as_ushort(__float2half_rn(v));
}
__device__ __forceinline__ void cpa16(uint32_t saddr, const void* g) {
    asm volatile("cp.async.cg.shared.global [%0], [%1], 16;" :: "r"(saddr), "l"(g));
}
#define CPA_COMMIT() asm volatile("cp.async.commit_group;" ::: "memory")
#define CPA_WAIT0()  asm volatile("cp.async.wait_group 0;" ::: "memory")

// ================= scratch =================
__device__ __align__(16) ushort_t g_Y [512u * 32768];       // fp16 [plane*256+h][pbc*32+y]
__device__ __align__(16) ushort_t g_Z [128u * 32768];       // fp16 [plane*64+j][col]
__device__ __align__(16) ushort_t g_Z3[128u * 32768];       // fp16
__device__ __align__(16) ushort_t g_V [262144u * 64];       // fp16 [row][plane*32+y]
__device__ __align__(16) ushort_t g_T1[256 * 64];           // fp16 [k=w][n]
__device__ __align__(16) ushort_t g_A2[128 * 512];          // fp16 [row][k]
__device__ __align__(16) ushort_t g_A4[512 * 128];          // fp16 [row][k]
__device__ __align__(16) ushort_t g_T5[64 * 256];           // fp16 [k|32+k][w], UNSCALED

// ================= table init (all single RN fp16) =================
__global__ void init_tables() {
    int t = blockIdx.x * 256 + threadIdx.x;   // 0..65535
    if (t < 256 * 64) {     // T1 [w][c]: c<32 cos, c>=32 -sin
        int w = t >> 6, c = t & 63, y = c & 31;
        int m = (w * y) & 255;
        double s, ct; sincospi(2.0 * m / 256.0, &s, &ct);
        g_T1[t] = h1((c < 32) ? (float)ct : (float)(-s));
    }
    {                       // A2 128x512
        int r = t >> 9, k = t & 511;
        int pk = k >> 8, hh = k & 255;
        int j = r & 63;
        int xr = (j < 32) ? j : (192 + j);
        int m = (xr * hh) & 255;
        double s, ct; sincospi(2.0 * m / 256.0, &s, &ct);
        float v;
        if (r < 64) v = (pk == 0) ? (float)ct : (float)s;
        else        v = (pk == 0) ? (float)(-s) : (float)ct;
        g_A2[t] = h1(v);
    }
    {                       // A4 512x128
        int r = t >> 7, c = t & 127;
        int pr = r >> 8, hh = r & 255;
        int pc = c >> 6, j = c & 63;
        int xr = (j < 32) ? j : (192 + j);
        int m = (xr * hh) & 255;
        double s, ct; sincospi(2.0 * m / 256.0, &s, &ct);
        float v;
        if (pr == 0) v = (pc == 0) ? (float)ct : (float)(-s);
        else         v = (pc == 0) ? (float)s  : (float)ct;
        g_A4[t] = h1(v);
    }
    if (t < 64 * 256) {     // T5 [k|32+k][w], UNSCALED c_k; 1/65536 in S5 epilogue
        int r = t >> 8, w = t & 255, k = r & 31;
        int m = (k * w) & 255;
        double s, ct; sincospi(2.0 * m / 256.0, &s, &ct);
        double coef = (k == 0) ? 1.0 : 2.0;
        g_T5[t] = h1((r < 32) ? (float)(coef * ct) : (float)(-coef * s));
    }
}

// ================= double-buffered cp.async fp16 single-pass warp-MMA GEMM =================
// C(M x NTOT) = A(M x KDIM) * B(KDIM x NTOT). One MMA pass.
// AMODE 0: A fp32 -> fp16 in-kernel.  AMODE 2: A fp16 via cp.async.
// CMODE 1: -> g_Y fp16 plane scatter (staged).  CMODE 2: -> g_V fp16 emit.
// CMODE 3: row-major f32 staged, scaled by 1/65536.  CMODE 4: -> g_Z fp16 row-major emit.
// OCC: min blocks per SM for __launch_bounds__.
template<int BM, int BN, int BK, int WM, int WN, long KDIM, long NTOT,
         int AMODE, int CMODE, int OCC>
__global__ void __launch_bounds__(256, OCC) mgemm(
    const float* __restrict__ Af, const ushort_t* __restrict__ Ahg,
    const ushort_t* __restrict__ Bhg, float* __restrict__ Cf)
{
    constexpr int TWM = BM / WM, TWN = BN / WN, MT = TWM / 16, NT = TWN / 8;
    constexpr int BKP = BK + 8, BNP = BN + 8;
    constexpr int PA = BM * BKP * 2;            // bytes per A plane
    constexpr int PB = BK * BNP * 2;            // bytes per B plane
    constexpr int OB0 = PA;
    constexpr int SBUF = PA + PB;
    constexpr long KT = KDIM / BK;
    constexpr int NBUF = (KT > 1) ? 2 : 1;
    constexpr int AF4 = BM * BK / 1024;         // float4/thread (AMODE 0)
    constexpr int AF8 = BM * BK / 2048;         // 16B cp.async/thread for A
    constexpr int BF8 = BK * BN / 2048;
    static_assert(WM * WN == 8 && (NT % 2) == 0, "cfg");

    extern __shared__ char smem[];
    const uint32_t sb = smem_u32(smem);
    const int t = threadIdx.x, wid = t >> 5, lane = t & 31;
    const int wm = wid / WN, wn = wid % WN;
    const long rowBase = (long)blockIdx.x * BM;
    const long colBase = (long)blockIdx.y * BN;

    float4 aReg[AMODE == 0 ? AF4 : 1];
    float  acc[MT][NT][4];
#pragma unroll
    for (int i = 0; i < MT; ++i)
#pragma unroll
        for (int j = 0; j < NT; ++j)
#pragma unroll
            for (int q = 0; q < 4; ++q) acc[i][j][q] = 0.f;

    auto fetchAsync = [&](long k0, int buf) {
        const uint32_t bb = sb + buf * SBUF;
        if constexpr (AMODE == 2) {
#pragma unroll
            for (int f8 = 0; f8 < AF8; ++f8) {
                int f = t + f8 * 256;
                int ar = f / (BK / 8), ac8 = f % (BK / 8);
                uint32_t off = (uint32_t)(ar * BKP + ac8 * 8) * 2;
                cpa16(bb + off, &Ahg[(rowBase + ar) * KDIM + k0 + ac8 * 8]);
            }
        }
#pragma unroll
        for (int f8 = 0; f8 < BF8; ++f8) {
            int f = t + f8 * 256;
            int br = f / (BN / 8), bc8 = f % (BN / 8);
            uint32_t off = (uint32_t)(br * BNP + bc8 * 8) * 2;
            cpa16(bb + OB0 + off, &Bhg[(k0 + br) * NTOT + colBase + bc8 * 8]);
        }
    };
    auto loadA = [&](long k0) {   // AMODE 0 only
#pragma unroll
        for (int f4 = 0; f4 < AF4; ++f4) {
            int f = t + f4 * 256;
            int ar = f / (BK / 4), ac = f % (BK / 4);
            aReg[f4] = *reinterpret_cast<const float4*>(
                &Af[(rowBase + ar) * KDIM + k0 + ac * 4]);
        }
    };
    auto storeA = [&](int buf) {  // AMODE 0 only
#pragma unroll
        for (int f4 = 0; f4 < AF4; ++f4) {
            int f = t + f4 * 256;
            int ar = f / (BK / 4), ac = f % (BK / 4);
            ushort_t q0 = h1(aReg[f4].x), q1 = h1(aReg[f4].y);
            ushort_t q2 = h1(aReg[f4].z), q3 = h1(aReg[f4].w);
            uint32_t off = buf * SBUF + (uint32_t)(ar * BKP + ac * 4) * 2;
            *reinterpret_cast<uint2*>(smem + off) =
                make_uint2(q0 | ((uint32_t)q1 << 16), q2 | ((uint32_t)q3 << 16));
        }
    };
    auto compute = [&](int buf) {
        const uint32_t bb = sb + buf * SBUF;
#pragma unroll
        for (int ks = 0; ks < BK / 16; ++ks) {
            const int k0 = ks * 16;
            uint32_t a0[MT][4];
#pragma unroll
            for (int i = 0; i < MT; ++i) {
                int row = wm * TWM + i * 16 + (lane & 15);
                int col = k0 + ((lane >> 4) << 3);
                ldm4(a0[i], bb + (uint32_t)(row * BKP + col) * 2);
            }
#pragma unroll
            for (int pr = 0; pr < NT / 2; ++pr) {
                uint32_t b0[4];
                int krow = k0 + ((lane >> 3) & 1) * 8 + (lane & 7);
                int coln = wn * TWN + (pr * 2 + (lane >> 4)) * 8;
                ldm4t(b0, bb + OB0 + (uint32_t)(krow * BNP + coln) * 2);
#pragma unroll
                for (int i = 0; i < MT; ++i)
#pragma unroll
                    for (int nn = 0; nn < 2; ++nn)
                        mma16816(acc[i][pr * 2 + nn], a0[i], b0 + nn * 2);
            }
        }
    };

    // prologue
    fetchAsync(0, 0);
    CPA_COMMIT();
    if constexpr (AMODE == 0) loadA(0);
    CPA_WAIT0();
    if constexpr (AMODE == 0) storeA(0);
    __syncthreads();

#pragma unroll 1
    for (long kt = 0; kt < KT; ++kt) {
        const int cur = (int)(kt % NBUF);
        const bool more = (kt + 1 < KT);
        if (more) {
            fetchAsync((kt + 1) * BK, cur ^ 1);
            CPA_COMMIT();
            if constexpr (AMODE == 0) loadA((kt + 1) * BK);
        }
        compute(cur);
        if (more) {
            if constexpr (AMODE == 0) storeA(cur ^ 1);
            CPA_WAIT0();
            __syncthreads();
        }
    }

    const int g = lane >> 2, tq = lane & 3;
    if constexpr (CMODE == 4) {
#pragma unroll
        for (int i = 0; i < MT; ++i)
#pragma unroll
            for (int j = 0; j < NT; ++j) {
                const float* c = acc[i][j];
                long r0 = rowBase + wm * TWM + i * 16 + g;
                long c0 = colBase + wn * TWN + j * 8 + tq * 2;
#pragma unroll
                for (int rr = 0; rr < 2; ++rr) {
                    ushort_t q0 = h1(c[rr * 2]), q1 = h1(c[rr * 2 + 1]);
                    *reinterpret_cast<uint32_t*>(&g_Z[(r0 + rr * 8) * NTOT + c0]) =
                        q0 | ((uint32_t)q1 << 16);
                }
            }
    } else if constexpr (CMODE == 2) {
#pragma unroll
        for (int i = 0; i < MT; ++i)
#pragma unroll
            for (int j = 0; j < NT; ++j) {
                const float* c = acc[i][j];
                long r0 = rowBase + wm * TWM + i * 16 + g;
                long c0 = colBase + wn * TWN + j * 8 + tq * 2;
                long pbc = c0 >> 5, y = c0 & 31;
#pragma unroll
                for (int rr = 0; rr < 2; ++rr) {
                    long r = r0 + rr * 8;
                    long plane = r >> 8, h = r & 255;
                    long addr = (pbc * 256 + h) * 64 + plane * 32 + y;
                    ushort_t q0 = h1(c[rr * 2]), q1 = h1(c[rr * 2 + 1]);
                    *reinterpret_cast<uint32_t*>(&g_V[addr]) = q0 | ((uint32_t)q1 << 16);
                }
            }
    } else {
        // staged: CMODE 1 (Y fp16 plane scatter) / CMODE 3 (f32 row-major scaled)
        float* stage = reinterpret_cast<float*>(smem);
        __syncthreads();
#pragma unroll
        for (int i = 0; i < MT; ++i)
#pragma unroll
            for (int j = 0; j < NT; ++j) {
                const float* c = acc[i][j];
                int row = wm * TWM + i * 16 + g;
                int col = wn * TWN + j * 8 + tq * 2;
                *reinterpret_cast<float2*>(&stage[row * (BN + 4) + col])       = make_float2(c[0], c[1]);
                *reinterpret_cast<float2*>(&stage[(row + 8) * (BN + 4) + col]) = make_float2(c[2], c[3]);
            }
        __syncthreads();
        if constexpr (CMODE == 1) {
            const long pbc = rowBase >> 8;
            const int hb = (int)(rowBase & 255);
#pragma unroll
            for (int it = 0; it < BM * BN / 1024; ++it) {
                int idx = t + it * 256;
                int r = idx / (BN / 4), c4 = idx % (BN / 4);
                float4 v = *reinterpret_cast<float4*>(&stage[r * (BN + 4) + c4 * 4]);
                int c = c4 * 4, plane = c >> 5, y = c & 31;
                ushort_t q0 = h1(v.x), q1 = h1(v.y), q2 = h1(v.z), q3 = h1(v.w);
                long addr = (long)(plane * 256 + hb + r) * 32768L + pbc * 32 + y;
                *reinterpret_cast<uint2*>(&g_Y[addr]) =
                    make_uint2(q0 | ((uint32_t)q1 << 16), q2 | ((uint32_t)q3 << 16));
            }
        } else {
#pragma unroll
            for (int it = 0; it < BM * BN / 1024; ++it) {
                int idx = t + it * 256;
                int r = idx / (BN / 4), c4 = idx % (BN / 4);
                float4 v = *reinterpret_cast<float4*>(&stage[r * (BN + 4) + c4 * 4]);
                constexpr float SC = 1.0f / 65536.0f;
                v.x *= SC; v.y *= SC; v.z *= SC; v.w *= SC;
                *reinterpret_cast<float4*>(&Cf[(rowBase + r) * NTOT + colBase + c4 * 4]) = v;
            }
        }
    }
}

// ================= channel mix: Z fp16 input, one-time fp32 reg cache =================
__global__ void __launch_bounds__(256, 2) chanmix(const ushort_t* __restrict__ Z,
                                                  const float* __restrict__ w1re,
                                                  const float* __restrict__ w1im,
                                                  const float* __restrict__ w4re,
                                                  const float* __restrict__ w4im) {
    __shared__ ushort_t Zs[2][128][32];       // [plane][b*32+i][y] 16 KB
    __shared__ float Ws[2][2][2][32][32];     // [grp][buf][plane][i][y] 32 KB
    const int t = threadIdx.x;
    const int p = blockIdx.x >> 6;
    const int j = blockIdx.x & 63;
    const int x = j & 31;
    const float* wre = (j < 32) ? w1re : w4re;
    const float* wim = (j < 32) ? w1im : w4im;

    // load Z tile (fp16): 2 planes x 128 bi x 32 y = 1024 uint4
#pragma unroll
    for (int pass = 0; pass < 4; ++pass) {
        int f = t + pass * 256;
        int plane = f >> 9;
        int rem = f & 511;
        int bi = rem >> 2;
        int y8 = rem & 3;
        uint4 v = *reinterpret_cast<const uint4*>(
            &Z[(size_t)(plane * 64 + j) * 32768 + (size_t)(p * 128 + bi) * 32 + y8 * 8]);
        *reinterpret_cast<uint4*>(&Zs[plane][bi][y8 * 8]) = v;
    }
    __syncthreads();

    const int og = t >> 7;
    const int t2 = t & 127;
    const int bb = (t2 >> 5) & 3;
    const int y  = t & 31;

    // one-time conversion into fp32 registers (no in-loop converts)
    float zre[32], zim[32];
#pragma unroll
    for (int i = 0; i < 32; ++i) {
        zre[i] = __half2float(__ushort_as_half(Zs[0][bb * 32 + i][y]));
        zim[i] = __half2float(__ushort_as_half(Zs[1][bb * 32 + i][y]));
    }

    auto fetchW = [&](int o, int buf) {
#pragma unroll
        for (int pass = 0; pass < 4; ++pass) {
            int f = t2 + pass * 128;
            int plane = f >> 8;
            int i = (f >> 3) & 31;
            int seg = f & 7;
            const float* wp = plane ? wim : wre;
            const float* gp = &wp[((((size_t)(i * 32 + o)) * 8 + p) * 32 + x) * 32 + seg * 4];
            cpa16(smem_u32(&Ws[og][buf][plane][i][seg * 4]), gp);
        }
    };

    fetchW(og * 16, 0);
    CPA_COMMIT();
    CPA_WAIT0();
    __syncthreads();

#pragma unroll 1
    for (int ol = 0; ol < 16; ++ol) {
        const int o = og * 16 + ol;
        const bool more = (ol + 1 < 16);
        if (more) {
            fetchW(o + 1, (ol + 1) & 1);
            CPA_COMMIT();
        }
        const int buf = ol & 1;
        float accre = 0.f, accim = 0.f;
#pragma unroll
        for (int i = 0; i < 32; ++i) {
            float wr = Ws[og][buf][0][i][y];
            float wi = Ws[og][buf][1][i][y];
            accre += zre[i] * wr - zim[i] * wi;
            accim += zre[i] * wi + zim[i] * wr;
        }
        size_t col = (size_t)(p * 128 + bb * 32 + o) * 32 + y;
        g_Z3[(size_t)j * 32768 + col]        = h1(accre);
        g_Z3[(size_t)(64 + j) * 32768 + col] = h1(accim);
        if (more) {
            CPA_WAIT0();
            __syncthreads();
        }
    }
}

// ================= launch =================
extern "C" void kernel_launch(void* const* d_in, const int* in_sizes, int n_in,
                              void* d_out, int out_size) {
    const float* x    = (const float*)d_in[0];
    const float* w1re = (const float*)d_in[1];
    const float* w1im = (const float*)d_in[2];
    const float* w4re = (const float*)d_in[3];
    const float* w4im = (const float*)d_in[4];
    float* out = (float*)d_out;

    void *pY, *pZ, *pZ3, *pV, *pT1, *pA2, *pA4, *pT5;
    cudaGetSymbolAddress(&pY,  g_Y);
    cudaGetSymbolAddress(&pZ,  g_Z);
    cudaGetSymbolAddress(&pZ3, g_Z3);
    cudaGetSymbolAddress(&pV,  g_V);
    cudaGetSymbolAddress(&pT1, g_T1);
    cudaGetSymbolAddress(&pA2, g_A2);
    cudaGetSymbolAddress(&pA4, g_A4);
    cudaGetSymbolAddress(&pT5, g_T5);

    // S1: A = x fp32 -> fp16; B = T1 (1 pass).  SBUF = 27648, x2 buf
    auto s1k = mgemm<128, 64, 64, 4, 2, 256L, 64L, 0, 1, 2>;
    // S2: A = A2; B = Y (1 pass) -> g_Z fp16.  3 CTAs/SM.
    auto s2k = mgemm<128, 64, 64, 4, 2, 512L, 32768L, 2, 4, 3>;
    // S4: A = A4; B = Z3 (1 pass) -> g_V fp16.  3 CTAs/SM.
    auto s4k = mgemm<128, 64, 64, 4, 2, 128L, 32768L, 2, 2, 3>;
    // S5: A = V; B = T5 (1 pass) -> out f32 staged/scaled.  3 CTAs/SM.
    auto s5k = mgemm<64, 128, 64, 2, 4, 64L, 256L, 2, 3, 3>;
    cudaFuncSetAttribute(s1k, cudaFuncAttributeMaxDynamicSharedMemorySize, 55296);
    cudaFuncSetAttribute(s2k, cudaFuncAttributeMaxDynamicSharedMemorySize, 55296);
    cudaFuncSetAttribute(s4k, cudaFuncAttributeMaxDynamicSharedMemorySize, 55296);
    cudaFuncSetAttribute(s5k, cudaFuncAttributeMaxDynamicSharedMemorySize, 34816);

    init_tables<<<256, 256>>>();

    // S1: Y(262144x64) = x(262144x256) * T1(256x64) -> Y fp16 plane scatter
    s1k<<<dim3(2048, 1), 256, 55296>>>(x, nullptr, (const ushort_t*)pT1, nullptr);

    // S2: Z(128x32768) = A2(128x512) * Y(512x32768) -> g_Z fp16
    s2k<<<dim3(1, 512), 256, 55296>>>(nullptr, (const ushort_t*)pA2,
                                      (const ushort_t*)pY, nullptr);

    // S3: channel mixing (reads Z fp16, emits Z3 fp16)
    chanmix<<<512, 256>>>((const ushort_t*)pZ, w1re, w1im, w4re, w4im);

    // S4: V(512x32768) = A4(512x128) * Z3(128x32768) -> g_V fp16
    s4k<<<dim3(4, 512), 256, 55296>>>(nullptr, (const ushort_t*)pA4,
                                      (const ushort_t*)pZ3, nullptr);

    // S5: out(262144x256) = V(262144x64) * T5(64x256), scaled 1/65536 in epilogue
    s5k<<<dim3(4096, 2), 256, 34816>>>(nullptr, (const ushort_t*)pV,
                                       (const ushort_t*)pT5, out);
}